// round 11
// baseline (speedup 1.0000x reference)
#include <cuda_runtime.h>
#include <cuda_bf16.h>
#include <cstdint>

#define NB   2048
#define NN   64
#define NPAD 132
#define NEG_BIG (-9000000000000000.0f)

// smem float offsets
#define OFF_Y0   0          // Y buffer 0 | ATT tile (e-phase / att@S)
#define OFF_X    8704       // persistent sate bf16 hi/lo tile
#define OFF_Y1   17408      // Y buffer 1 | fp32 sate copy | gate W (+A spill)
#define OFF_A    26112      // a_k fp32 (dead at gate; W spills here)
#define OFF_STAR 26624
#define OFF_V2A  26752
#define OFF_V2B  26880
#define OFF_MS   27008
#define OFF_BR   27072
#define OFF_PA   27136
#define OFF_PB   27264
#define SM_FLOATS 27392
#define SM_BYTES (SM_FLOATS*4 + 64*68)   // 113920

#define TS    272
#define THALF 17408
#define ATT_S 144
#define ATT_HALF 9216
#define GWS   144
#define GWHALF (128*144)

__device__ float g_M1[16384];   // q1 @ k1^T  row-major
__device__ float g_M2[16384];   // k2 @ q2^T  row-major

__device__ __forceinline__ uint32_t smem_u32(const void* p) {
    uint32_t a;
    asm("{ .reg .u64 t; cvta.to.shared.u64 t, %1; cvt.u32.u64 %0, t; }" : "=r"(a) : "l"(p));
    return a;
}
__device__ __forceinline__ uint32_t pack_bf2(__nv_bfloat16 a, __nv_bfloat16 b) {
    __nv_bfloat162 v = __halves2bfloat162(a, b);
    return *reinterpret_cast<uint32_t*>(&v);
}
__device__ __forceinline__ void cvt_hilo(float2 v, uint32_t& hi, uint32_t& lo) {
    __nv_bfloat16 h0 = __float2bfloat16_rn(v.x), h1 = __float2bfloat16_rn(v.y);
    hi = pack_bf2(h0, h1);
    lo = pack_bf2(__float2bfloat16_rn(v.x - __bfloat162float(h0)),
                  __float2bfloat16_rn(v.y - __bfloat162float(h1)));
}
// reconstruct fp32 pair from X tile hi/lo words
__device__ __forceinline__ float2 xval(const char* XT, int off) {
    uint32_t uh = *reinterpret_cast<const uint32_t*>(XT + off);
    uint32_t ul = *reinterpret_cast<const uint32_t*>(XT + THALF + off);
    __nv_bfloat162 vh = *reinterpret_cast<__nv_bfloat162*>(&uh);
    __nv_bfloat162 vl = *reinterpret_cast<__nv_bfloat162*>(&ul);
    return make_float2(__bfloat162float(vh.x) + __bfloat162float(vl.x),
                       __bfloat162float(vh.y) + __bfloat162float(vl.y));
}

#define LDSM4(r, addr) \
    asm volatile("ldmatrix.sync.aligned.m8n8.x4.shared.b16 {%0,%1,%2,%3}, [%4];" \
        : "=r"((r)[0]), "=r"((r)[1]), "=r"((r)[2]), "=r"((r)[3]) : "r"(addr))
#define LDSM2(r0, r1, addr) \
    asm volatile("ldmatrix.sync.aligned.m8n8.x2.shared.b16 {%0,%1}, [%2];" \
        : "=r"(r0), "=r"(r1) : "r"(addr))
#define LDSM2T(r0, r1, addr) \
    asm volatile("ldmatrix.sync.aligned.m8n8.x2.trans.shared.b16 {%0,%1}, [%2];" \
        : "=r"(r0), "=r"(r1) : "r"(addr))
#define MMA16816(c0,c1,c2,c3, a, b0,b1) \
    asm volatile("mma.sync.aligned.m16n8k16.row.col.f32.bf16.bf16.f32 " \
        "{%0,%1,%2,%3}, {%4,%5,%6,%7}, {%8,%9}, {%0,%1,%2,%3};" \
        : "+f"(c0), "+f"(c1), "+f"(c2), "+f"(c3) \
        : "r"((a)[0]), "r"((a)[1]), "r"((a)[2]), "r"((a)[3]), "r"(b0), "r"(b1))

// build 64x128 hi/lo tile of (sate * vec) reading sate from the X tile
__device__ __forceinline__ void build_from_X(const char* XT, const float* vec,
                                             char* tile, int tid) {
    for (int p = tid; p < 4096; p += 256) {
        int row = p >> 6, d = (p & 63) << 1;
        int off = row * TS + d * 2;
        float2 s = xval(XT, off);
        uint32_t hi, lo;
        cvt_hilo(make_float2(s.x * vec[d], s.y * vec[d + 1]), hi, lo);
        *reinterpret_cast<uint32_t*>(tile + off)         = hi;
        *reinterpret_cast<uint32_t*>(tile + THALF + off) = lo;
    }
}

__global__ void prep_kernel(const float* __restrict__ q1, const float* __restrict__ k1,
                            const float* __restrict__ q2, const float* __restrict__ k2) {
    int o = blockIdx.x * 256 + threadIdx.x;
    int m = o >> 14, idx = o & 16383;
    int t = idx >> 7, c = idx & 127;
    const float* X = m ? k2 : q1;
    const float* Y = m ? q2 : k1;
    float acc = 0.f;
    const float4* xr = reinterpret_cast<const float4*>(X + t * 128);
    const float4* yr = reinterpret_cast<const float4*>(Y + c * 128);
    #pragma unroll 8
    for (int d = 0; d < 32; d++) {
        float4 xv = xr[d], yv = yr[d];
        acc += xv.x * yv.x + xv.y * yv.y + xv.z * yv.z + xv.w * yv.w;
    }
    (m ? g_M2 : g_M1)[t * 128 + c] = acc;
}

__global__ void __launch_bounds__(256, 2)
star_agg_kernel(const float* __restrict__ hidden, const int* __restrict__ adj,
                const float* __restrict__ mask,
                const float* __restrict__ a0, const float* __restrict__ a1,
                const float* __restrict__ a2, const float* __restrict__ a3,
                const float* __restrict__ wlin,
                float* __restrict__ outp, float* __restrict__ starp)
{
    extern __shared__ float sm[];
    float* AK   = sm + OFF_A;
    float* STAR = sm + OFF_STAR;
    float* V2A  = sm + OFF_V2A;
    float* V2B  = sm + OFF_V2B;
    float* MS   = sm + OFF_MS;
    float* BR   = sm + OFF_BR;
    float* PA   = sm + OFF_PA;
    float* PB   = sm + OFF_PB;
    float* SF   = sm + OFF_Y1;              // fp32 sate copy (valid between blend and next build)
    char*  Y0T  = (char*)(sm + OFF_Y0);
    char*  XT   = (char*)(sm + OFF_X);
    char*  Y1T  = (char*)(sm + OFF_Y1);
    unsigned char* ADJ = (unsigned char*)(sm + SM_FLOATS);

    const int tid = threadIdx.x, lane = tid & 31, warp = tid >> 5, b = blockIdx.x;
    const uint32_t smb = smem_u32(sm);
    const uint32_t Y0H = smb;
    const uint32_t XH  = smb + OFF_X * 4;
    const uint32_t Y1H = smb + OFF_Y1 * 4;
    const float* hg = hidden + (size_t)b * (NN * 128);
    const int*   ag = adj + (size_t)b * (NN * NN);

    // hidden -> X tile directly
    for (int p = tid; p < 4096; p += 256) {
        int row = p >> 6, d = (p & 63) << 1;
        float2 h = __ldg(reinterpret_cast<const float2*>(&hg[row * 128 + d]));
        uint32_t hi, lo;
        cvt_hilo(h, hi, lo);
        int off = row * TS + d * 2;
        *reinterpret_cast<uint32_t*>(XT + off)         = hi;
        *reinterpret_cast<uint32_t*>(XT + THALF + off) = lo;
    }
    for (int idx = tid; idx < NN * NN; idx += 256)
        ADJ[(idx >> 6) * 68 + (idx & 63)] = (unsigned char)ag[idx];
    if (tid < 128) {
        AK[tid] = a0[tid]; AK[128 + tid] = a1[tid];
        AK[256 + tid] = a2[tid]; AK[384 + tid] = a3[tid];
    }
    if (tid < 64) MS[tid] = mask[b * NN + tid];
    __syncthreads();

    if (tid < 128) {
        float acc = 0.f, msum = 0.f;
        #pragma unroll 8
        for (int i = 0; i < NN; i++) { acc += hg[i * 128 + tid] * MS[i]; msum += MS[i]; }
        STAR[tid] = acc / msum;
    }
    __syncthreads();

    const float RSQ = 0.088388347648318447f;
    const int mstrip = warp & 3, nhalf = warp >> 2;
    const int R0 = mstrip * 16, N0 = nhalf * 32;
    const int g = lane >> 2, i0 = R0 + g;
    const int lsel = lane & 15;
    const int m4 = lane >> 3;
    const uint32_t abase = XH + (uint32_t)(R0 + (lane & 7) + ((m4 & 1) << 3)) * TS
                         + ((m4 >> 1) << 4);

    for (int step = 0; step < 2; step++) {
        // ===== star matvecs (row-major float4, parallel pairs) =====
        {
            const int gg = warp >> 2;
            const int t = tid & 127;
            const float* MT = gg ? g_M2 : g_M1;
            float* V2g = gg ? V2B : V2A;
            const float4* mr = reinterpret_cast<const float4*>(MT + t * 128);
            float acc = 0.f;
            #pragma unroll 8
            for (int d4 = 0; d4 < 32; d4++) {
                float4 mv = __ldg(&mr[d4]);
                float4 sv = *reinterpret_cast<const float4*>(&STAR[d4 * 4]);
                acc += mv.x * sv.x + mv.y * sv.y + mv.z * sv.z + mv.w * sv.w;
            }
            V2g[t] = acc;
        }

        // ===== A frags (X tile) =====
        uint32_t ah[32], al[32];
        #pragma unroll
        for (int kt = 0; kt < 8; kt++) {
            LDSM4(&ah[kt * 4], abase + kt * 32);
            LDSM4(&al[kt * 4], abase + THALF + kt * 32);
        }

        // ===== e-logits: double-buffered Y =====
        build_from_X(XT, AK, Y0T, tid);
        __syncthreads();
        float sel[4][4];
        #pragma unroll
        for (int nt = 0; nt < 4; nt++)
            #pragma unroll
            for (int q = 0; q < 4; q++) sel[nt][q] = NEG_BIG;

        #pragma unroll
        for (int k = 0; k < 4; k++) {
            const uint32_t curH = (k & 1) ? Y1H : Y0H;
            const uint32_t bb = curH + (uint32_t)(N0 + (lsel & 7)) * TS + ((lsel >> 3) << 4);
            float ce[4][4];
            #pragma unroll
            for (int nt = 0; nt < 4; nt++)
                #pragma unroll
                for (int q = 0; q < 4; q++) ce[nt][q] = 0.f;
            #pragma unroll
            for (int nt = 0; nt < 4; nt++) {
                #pragma unroll
                for (int kt = 0; kt < 8; kt++) {
                    uint32_t bh0, bh1, bl0, bl1;
                    uint32_t ba = bb + nt * (8 * TS) + kt * 32;
                    LDSM2(bh0, bh1, ba);
                    LDSM2(bl0, bl1, ba + THALF);
                    MMA16816(ce[nt][0], ce[nt][1], ce[nt][2], ce[nt][3], &ah[kt * 4], bh0, bh1);
                    MMA16816(ce[nt][0], ce[nt][1], ce[nt][2], ce[nt][3], &ah[kt * 4], bl0, bl1);
                    MMA16816(ce[nt][0], ce[nt][1], ce[nt][2], ce[nt][3], &al[kt * 4], bh0, bh1);
                }
            }
            int code = k + 1;
            #pragma unroll
            for (int nt = 0; nt < 4; nt++) {
                int j0 = N0 + nt * 8 + ((lane & 3) << 1);
                if (ADJ[i0 * 68 + j0] == code)
                    sel[nt][0] = (ce[nt][0] >= 0.f) ? ce[nt][0] : 0.2f * ce[nt][0];
                if (ADJ[i0 * 68 + j0 + 1] == code)
                    sel[nt][1] = (ce[nt][1] >= 0.f) ? ce[nt][1] : 0.2f * ce[nt][1];
                if (ADJ[(i0 + 8) * 68 + j0] == code)
                    sel[nt][2] = (ce[nt][2] >= 0.f) ? ce[nt][2] : 0.2f * ce[nt][2];
                if (ADJ[(i0 + 8) * 68 + j0 + 1] == code)
                    sel[nt][3] = (ce[nt][3] >= 0.f) ? ce[nt][3] : 0.2f * ce[nt][3];
            }
            if (k < 3) {
                build_from_X(XT, AK + (k + 1) * 128, (k & 1) ? Y0T : Y1T, tid);
                __syncthreads();
            }
        }

        // ===== fragment softmax (named 64-thread barriers) =====
        float m0 = NEG_BIG, m1 = NEG_BIG;
        #pragma unroll
        for (int nt = 0; nt < 4; nt++) {
            m0 = fmaxf(m0, fmaxf(sel[nt][0], sel[nt][1]));
            m1 = fmaxf(m1, fmaxf(sel[nt][2], sel[nt][3]));
        }
        m0 = fmaxf(m0, __shfl_xor_sync(0xffffffffu, m0, 1));
        m0 = fmaxf(m0, __shfl_xor_sync(0xffffffffu, m0, 2));
        m1 = fmaxf(m1, __shfl_xor_sync(0xffffffffu, m1, 1));
        m1 = fmaxf(m1, __shfl_xor_sync(0xffffffffu, m1, 2));
        if ((lane & 3) == 0) { PA[i0 * 2 + nhalf] = m0; PA[(i0 + 8) * 2 + nhalf] = m1; }
        asm volatile("bar.sync %0, 64;" :: "r"(1 + mstrip) : "memory");
        m0 = fmaxf(PA[i0 * 2], PA[i0 * 2 + 1]);
        m1 = fmaxf(PA[(i0 + 8) * 2], PA[(i0 + 8) * 2 + 1]);
        float s0 = 0.f, s1 = 0.f;
        #pragma unroll
        for (int nt = 0; nt < 4; nt++) {
            sel[nt][0] = __expf(sel[nt][0] - m0); s0 += sel[nt][0];
            sel[nt][1] = __expf(sel[nt][1] - m0); s0 += sel[nt][1];
            sel[nt][2] = __expf(sel[nt][2] - m1); s1 += sel[nt][2];
            sel[nt][3] = __expf(sel[nt][3] - m1); s1 += sel[nt][3];
        }
        s0 += __shfl_xor_sync(0xffffffffu, s0, 1);
        s0 += __shfl_xor_sync(0xffffffffu, s0, 2);
        s1 += __shfl_xor_sync(0xffffffffu, s1, 1);
        s1 += __shfl_xor_sync(0xffffffffu, s1, 2);
        if ((lane & 3) == 0) { PB[i0 * 2 + nhalf] = s0; PB[(i0 + 8) * 2 + nhalf] = s1; }
        asm volatile("bar.sync %0, 64;" :: "r"(1 + mstrip) : "memory");
        float inv0 = 1.f / (PB[i0 * 2] + PB[i0 * 2 + 1]);
        float inv1 = 1.f / (PB[(i0 + 8) * 2] + PB[(i0 + 8) * 2 + 1]);

        // ===== write ATT tile (Y0 region; Y0 last read at k=2, synced) =====
        #pragma unroll
        for (int nt = 0; nt < 4; nt++) {
            int j0 = N0 + nt * 8 + ((lane & 3) << 1);
            uint32_t hi, lo;
            cvt_hilo(make_float2(sel[nt][0] * inv0, sel[nt][1] * inv0), hi, lo);
            int off = i0 * ATT_S + j0 * 2;
            *reinterpret_cast<uint32_t*>(Y0T + off)            = hi;
            *reinterpret_cast<uint32_t*>(Y0T + ATT_HALF + off) = lo;
            cvt_hilo(make_float2(sel[nt][2] * inv1, sel[nt][3] * inv1), hi, lo);
            off = (i0 + 8) * ATT_S + j0 * 2;
            *reinterpret_cast<uint32_t*>(Y0T + off)            = hi;
            *reinterpret_cast<uint32_t*>(Y0T + ATT_HALF + off) = lo;
        }
        __syncthreads();

        // ===== T = att @ S (A = ATT, B = X^T) =====
        {
            uint32_t aah[16], aal[16];
            uint32_t tabase = Y0H + (uint32_t)(R0 + (lane & 7) + ((m4 & 1) << 3)) * ATT_S
                            + ((m4 >> 1) << 4);
            #pragma unroll
            for (int kt = 0; kt < 4; kt++) {
                LDSM4(&aah[kt * 4], tabase + kt * 32);
                LDSM4(&aal[kt * 4], tabase + ATT_HALF + kt * 32);
            }
            const int N0d = nhalf * 64;
            float tc[8][4];
            #pragma unroll
            for (int nt = 0; nt < 8; nt++)
                #pragma unroll
                for (int q = 0; q < 4; q++) tc[nt][q] = 0.f;
            #pragma unroll
            for (int nt = 0; nt < 8; nt++) {
                #pragma unroll
                for (int kt = 0; kt < 4; kt++) {
                    uint32_t bh0, bh1, bl0, bl1;
                    uint32_t ba = XH + (uint32_t)(kt * 16 + lsel) * TS + (uint32_t)(N0d + nt * 8) * 2;
                    LDSM2T(bh0, bh1, ba);
                    LDSM2T(bl0, bl1, ba + THALF);
                    MMA16816(tc[nt][0], tc[nt][1], tc[nt][2], tc[nt][3], &aah[kt * 4], bh0, bh1);
                    MMA16816(tc[nt][0], tc[nt][1], tc[nt][2], tc[nt][3], &aah[kt * 4], bl0, bl1);
                    MMA16816(tc[nt][0], tc[nt][1], tc[nt][2], tc[nt][3], &aal[kt * 4], bh0, bh1);
                }
            }

            float pa0 = 0.f, pa1 = 0.f;
            #pragma unroll
            for (int nt = 0; nt < 8; nt++) {
                int d0 = N0d + nt * 8 + ((lane & 3) << 1);
                float2 va = *reinterpret_cast<const float2*>(&V2A[d0]);
                pa0 += tc[nt][0] * va.x + tc[nt][1] * va.y;
                pa1 += tc[nt][2] * va.x + tc[nt][3] * va.y;
            }
            pa0 += __shfl_xor_sync(0xffffffffu, pa0, 1);
            pa0 += __shfl_xor_sync(0xffffffffu, pa0, 2);
            pa1 += __shfl_xor_sync(0xffffffffu, pa1, 1);
            pa1 += __shfl_xor_sync(0xffffffffu, pa1, 2);
            if ((lane & 3) == 0) { PA[i0 * 2 + nhalf] = pa0; PA[(i0 + 8) * 2 + nhalf] = pa1; }
            __syncthreads();    // PA exchange + X/Y1 write-after-read guard
            float al0 = (PA[i0 * 2] + PA[i0 * 2 + 1]) * RSQ;
            float al1 = (PA[(i0 + 8) * 2] + PA[(i0 + 8) * 2 + 1]) * RSQ;

            float pb0 = 0.f, pb1 = 0.f;
            #pragma unroll
            for (int nt = 0; nt < 8; nt++) {
                int d0 = N0d + nt * 8 + ((lane & 3) << 1);
                float2 st = *reinterpret_cast<const float2*>(&STAR[d0]);
                float2 vb = *reinterpret_cast<const float2*>(&V2B[d0]);
                float n0x = (1.f - al0) * tc[nt][0] + al0 * st.x;
                float n0y = (1.f - al0) * tc[nt][1] + al0 * st.y;
                float n1x = (1.f - al1) * tc[nt][2] + al1 * st.x;
                float n1y = (1.f - al1) * tc[nt][3] + al1 * st.y;
                *reinterpret_cast<float2*>(&SF[i0 * NPAD + d0])       = make_float2(n0x, n0y);
                *reinterpret_cast<float2*>(&SF[(i0 + 8) * NPAD + d0]) = make_float2(n1x, n1y);
                uint32_t hi, lo;
                int off = i0 * TS + d0 * 2;
                cvt_hilo(make_float2(n0x, n0y), hi, lo);
                *reinterpret_cast<uint32_t*>(XT + off)         = hi;
                *reinterpret_cast<uint32_t*>(XT + THALF + off) = lo;
                off = (i0 + 8) * TS + d0 * 2;
                cvt_hilo(make_float2(n1x, n1y), hi, lo);
                *reinterpret_cast<uint32_t*>(XT + off)         = hi;
                *reinterpret_cast<uint32_t*>(XT + THALF + off) = lo;
                pb0 += n0x * vb.x + n0y * vb.y;
                pb1 += n1x * vb.x + n1y * vb.y;
            }
            pb0 += __shfl_xor_sync(0xffffffffu, pb0, 1);
            pb0 += __shfl_xor_sync(0xffffffffu, pb0, 2);
            pb1 += __shfl_xor_sync(0xffffffffu, pb1, 1);
            pb1 += __shfl_xor_sync(0xffffffffu, pb1, 2);
            if ((lane & 3) == 0) { PB[i0 * 2 + nhalf] = pb0; PB[(i0 + 8) * 2 + nhalf] = pb1; }
        }
        __syncthreads();

        // ===== beta softmax + star update (reads fp32 SF) =====
        if (warp == 0) {
            float b0 = (MS[lane] == 0.f)      ? __int_as_float(0xff800000)
                                              : (PB[lane * 2] + PB[lane * 2 + 1]) * RSQ;
            float b1 = (MS[lane + 32] == 0.f) ? __int_as_float(0xff800000)
                                              : (PB[(lane + 32) * 2] + PB[(lane + 32) * 2 + 1]) * RSQ;
            float m = fmaxf(b0, b1);
            #pragma unroll
            for (int o = 16; o > 0; o >>= 1) m = fmaxf(m, __shfl_xor_sync(0xffffffffu, m, o));
            float e0 = __expf(b0 - m), e1 = __expf(b1 - m);
            float sE = e0 + e1;
            #pragma unroll
            for (int o = 16; o > 0; o >>= 1) sE += __shfl_xor_sync(0xffffffffu, sE, o);
            float inv = 1.f / sE;
            BR[lane] = e0 * inv; BR[lane + 32] = e1 * inv;
        }
        __syncthreads();
        if (tid < 128) {
            float acc = 0.f;
            #pragma unroll 8
            for (int j = 0; j < 64; j++) acc += BR[j] * SF[j * NPAD + tid];
            STAR[tid] = acc;
        }
        __syncthreads();
    }

    // ===== gate: C = cat(hidden,S) @ W^T ; W staged in Y1 (+A spill) =====
    {
        char* WT = Y1T;
        const uint32_t WTH = Y1H;
        const int N0g = nhalf * 64;
        float acc[8][4];
        #pragma unroll
        for (int nt = 0; nt < 8; nt++)
            #pragma unroll
            for (int q = 0; q < 4; q++) acc[nt][q] = 0.f;

        for (int chunk = 0; chunk < 4; chunk++) {
            const int c0 = chunk * 64;
            __syncthreads();
            for (int idx = tid; idx < 2048; idx += 256) {
                int o = idx >> 4, p4 = idx & 15;
                float4 w = __ldg(reinterpret_cast<const float4*>(&wlin[o * 256 + c0 + p4 * 4]));
                uint32_t h0, l0, h1, l1;
                cvt_hilo(make_float2(w.x, w.y), h0, l0);
                cvt_hilo(make_float2(w.z, w.w), h1, l1);
                uint2 uh = make_uint2(h0, h1), ul = make_uint2(l0, l1);
                *reinterpret_cast<uint2*>(WT + o * GWS + p4 * 8)          = uh;
                *reinterpret_cast<uint2*>(WT + GWHALF + o * GWS + p4 * 8) = ul;
            }
            __syncthreads();
            const bool fh2 = chunk < 2;
            const int cb = fh2 ? c0 : (c0 - 128);
            const int r0 = i0;
            #pragma unroll
            for (int kt = 0; kt < 4; kt++) {
                uint32_t fah[4], fal[4];
                if (fh2) {
                    int cc = cb + kt * 16 + ((lane & 3) << 1);
                    float2 x00 = __ldg(reinterpret_cast<const float2*>(&hg[r0 * 128 + cc]));
                    float2 x10 = __ldg(reinterpret_cast<const float2*>(&hg[(r0 + 8) * 128 + cc]));
                    float2 x01 = __ldg(reinterpret_cast<const float2*>(&hg[r0 * 128 + cc + 8]));
                    float2 x11 = __ldg(reinterpret_cast<const float2*>(&hg[(r0 + 8) * 128 + cc + 8]));
                    cvt_hilo(x00, fah[0], fal[0]);
                    cvt_hilo(x10, fah[1], fal[1]);
                    cvt_hilo(x01, fah[2], fal[2]);
                    cvt_hilo(x11, fah[3], fal[3]);
                } else {
                    uint32_t ab2 = abase + (uint32_t)(cb + kt * 16) * 2;
                    LDSM4(fah, ab2);
                    LDSM4(fal, ab2 + THALF);
                }
                uint32_t bb = WTH + (uint32_t)(N0g + (lsel & 7)) * GWS + ((lsel >> 3) << 4) + kt * 32;
                #pragma unroll
                for (int nt = 0; nt < 8; nt++) {
                    uint32_t bh0, bh1, bl0, bl1;
                    uint32_t ba = bb + nt * (8 * GWS);
                    LDSM2(bh0, bh1, ba);
                    LDSM2(bl0, bl1, ba + GWHALF);
                    MMA16816(acc[nt][0], acc[nt][1], acc[nt][2], acc[nt][3], fah, bh0, bh1);
                    MMA16816(acc[nt][0], acc[nt][1], acc[nt][2], acc[nt][3], fah, bl0, bl1);
                    MMA16816(acc[nt][0], acc[nt][1], acc[nt][2], acc[nt][3], fal, bh0, bh1);
                }
            }
        }

        float* ob = outp + (size_t)b * (NN * 128);
        const int r0 = i0;
        #pragma unroll
        for (int nt = 0; nt < 8; nt++) {
            int o0 = N0g + nt * 8 + ((lane & 3) << 1);
            float2 h0 = __ldg(reinterpret_cast<const float2*>(&hg[r0 * 128 + o0]));
            float2 h1 = __ldg(reinterpret_cast<const float2*>(&hg[(r0 + 8) * 128 + o0]));
            float2 s0v = xval(XT, r0 * TS + o0 * 2);
            float2 s1v = xval(XT, (r0 + 8) * TS + o0 * 2);
            float g00 = 1.f / (1.f + __expf(-acc[nt][0]));
            float g01 = 1.f / (1.f + __expf(-acc[nt][1]));
            float g10 = 1.f / (1.f + __expf(-acc[nt][2]));
            float g11 = 1.f / (1.f + __expf(-acc[nt][3]));
            float2 r0v, r1v;
            r0v.x = g00 * h0.x + (1.f - g00) * s0v.x;
            r0v.y = g01 * h0.y + (1.f - g01) * s0v.y;
            r1v.x = g10 * h1.x + (1.f - g10) * s1v.x;
            r1v.y = g11 * h1.y + (1.f - g11) * s1v.y;
            *reinterpret_cast<float2*>(&ob[r0 * 128 + o0])       = r0v;
            *reinterpret_cast<float2*>(&ob[(r0 + 8) * 128 + o0]) = r1v;
        }
    }
    if (tid < 128) starp[(size_t)b * 128 + tid] = STAR[tid];
}

extern "C" void kernel_launch(void* const* d_in, const int* in_sizes, int n_in,
                              void* d_out, int out_size) {
    float* outp  = (float*)d_out;
    float* starp = outp + (size_t)NB * NN * 128;

    prep_kernel<<<128, 256>>>((const float*)d_in[7], (const float*)d_in[8],
                              (const float*)d_in[9], (const float*)d_in[10]);
    cudaFuncSetAttribute(star_agg_kernel, cudaFuncAttributeMaxDynamicSharedMemorySize, SM_BYTES);
    star_agg_kernel<<<NB, 256, SM_BYTES>>>(
        (const float*)d_in[0], (const int*)d_in[1], (const float*)d_in[2],
        (const float*)d_in[3], (const float*)d_in[4], (const float*)d_in[5], (const float*)d_in[6],
        (const float*)d_in[11], outp, starp);
}

// round 12
// speedup vs baseline: 1.0464x; 1.0464x over previous
#include <cuda_runtime.h>
#include <cuda_bf16.h>
#include <cstdint>

#define NB   2048
#define NN   64
#define NPAD 132
#define NEG_BIG (-9000000000000000.0f)

#define OFF_S    0          // 64*132 fp32
#define OFF_X    8448       // persistent S bf16 hi/lo tile (34816B)
#define OFF_Y    17152      // Y_k tile | ATT tile | gate W staging
#define OFF_A    25856      // a_k
#define OFF_STAR 26368
#define OFF_V2A  26496
#define OFF_V2B  26624
#define OFF_MS   26752
#define OFF_BR   26816
#define OFF_PA   26880
#define OFF_PB   27008
#define SM_FLOATS 27136
#define SM_BYTES (SM_FLOATS*4 + 64*68)

#define TS    272
#define THALF 17408
#define ATT_S 144
#define ATT_HALF 9216
#define GWS   144
#define GWHALF (128*144)

__device__ float g_M1[16384];   // q1 @ k1^T  row-major
__device__ float g_M2[16384];   // k2 @ q2^T  row-major

__device__ __forceinline__ uint32_t smem_u32(const void* p) {
    uint32_t a;
    asm("{ .reg .u64 t; cvta.to.shared.u64 t, %1; cvt.u32.u64 %0, t; }" : "=r"(a) : "l"(p));
    return a;
}
__device__ __forceinline__ uint32_t pack_bf2(__nv_bfloat16 a, __nv_bfloat16 b) {
    __nv_bfloat162 v = __halves2bfloat162(a, b);
    return *reinterpret_cast<uint32_t*>(&v);
}
__device__ __forceinline__ void cvt_hilo(float2 v, uint32_t& hi, uint32_t& lo) {
    __nv_bfloat16 h0 = __float2bfloat16_rn(v.x), h1 = __float2bfloat16_rn(v.y);
    hi = pack_bf2(h0, h1);
    lo = pack_bf2(__float2bfloat16_rn(v.x - __bfloat162float(h0)),
                  __float2bfloat16_rn(v.y - __bfloat162float(h1)));
}

#define LDSM4(r, addr) \
    asm volatile("ldmatrix.sync.aligned.m8n8.x4.shared.b16 {%0,%1,%2,%3}, [%4];" \
        : "=r"((r)[0]), "=r"((r)[1]), "=r"((r)[2]), "=r"((r)[3]) : "r"(addr))
#define LDSM2(r0, r1, addr) \
    asm volatile("ldmatrix.sync.aligned.m8n8.x2.shared.b16 {%0,%1}, [%2];" \
        : "=r"(r0), "=r"(r1) : "r"(addr))
#define LDSM2T(r0, r1, addr) \
    asm volatile("ldmatrix.sync.aligned.m8n8.x2.trans.shared.b16 {%0,%1}, [%2];" \
        : "=r"(r0), "=r"(r1) : "r"(addr))
#define MMA16816(c0,c1,c2,c3, a, b0,b1) \
    asm volatile("mma.sync.aligned.m16n8k16.row.col.f32.bf16.bf16.f32 " \
        "{%0,%1,%2,%3}, {%4,%5,%6,%7}, {%8,%9}, {%0,%1,%2,%3};" \
        : "+f"(c0), "+f"(c1), "+f"(c2), "+f"(c3) \
        : "r"((a)[0]), "r"((a)[1]), "r"((a)[2]), "r"((a)[3]), "r"(b0), "r"(b1))

__device__ __forceinline__ void build_tile(const float* S, const float* vec,
                                           char* tile, int tid) {
    for (int p = tid; p < 4096; p += 256) {
        int row = p >> 6, d = (p & 63) << 1;
        float2 sv = *reinterpret_cast<const float2*>(&S[row * NPAD + d]);
        float x0 = sv.x, x1 = sv.y;
        if (vec) { x0 *= vec[d]; x1 *= vec[d + 1]; }
        uint32_t hi, lo;
        cvt_hilo(make_float2(x0, x1), hi, lo);
        int off = row * TS + d * 2;
        *reinterpret_cast<uint32_t*>(tile + off)         = hi;
        *reinterpret_cast<uint32_t*>(tile + THALF + off) = lo;
    }
}

__global__ void prep_kernel(const float* __restrict__ q1, const float* __restrict__ k1,
                            const float* __restrict__ q2, const float* __restrict__ k2) {
    int o = blockIdx.x * 256 + threadIdx.x;
    int m = o >> 14, idx = o & 16383;
    int t = idx >> 7, c = idx & 127;
    const float* X = m ? k2 : q1;
    const float* Y = m ? q2 : k1;
    float acc = 0.f;
    const float4* xr = reinterpret_cast<const float4*>(X + t * 128);
    const float4* yr = reinterpret_cast<const float4*>(Y + c * 128);
    #pragma unroll 8
    for (int d = 0; d < 32; d++) {
        float4 xv = xr[d], yv = yr[d];
        acc += xv.x * yv.x + xv.y * yv.y + xv.z * yv.z + xv.w * yv.w;
    }
    (m ? g_M2 : g_M1)[t * 128 + c] = acc;   // row-major
}

__global__ void __launch_bounds__(256, 2)
star_agg_kernel(const float* __restrict__ hidden, const int* __restrict__ adj,
                const float* __restrict__ mask,
                const float* __restrict__ a0, const float* __restrict__ a1,
                const float* __restrict__ a2, const float* __restrict__ a3,
                const float* __restrict__ wlin,
                float* __restrict__ outp, float* __restrict__ starp)
{
    extern __shared__ float sm[];
    float* S    = sm + OFF_S;
    float* A    = sm + OFF_A;
    float* STAR = sm + OFF_STAR;
    float* V2A  = sm + OFF_V2A;
    float* V2B  = sm + OFF_V2B;
    float* MS   = sm + OFF_MS;
    float* BR   = sm + OFF_BR;
    float* PA   = sm + OFF_PA;
    float* PB   = sm + OFF_PB;
    char*  XT   = (char*)(sm + OFF_X);
    char*  YT   = (char*)(sm + OFF_Y);
    unsigned char* ADJ = (unsigned char*)(sm + SM_FLOATS);  // [i][j] stride 68

    const int tid = threadIdx.x, lane = tid & 31, warp = tid >> 5, b = blockIdx.x;
    const uint32_t smb = smem_u32(sm);
    const uint32_t XH = smb + OFF_X * 4;
    const uint32_t YH = smb + OFF_Y * 4;
    const float* hg = hidden + (size_t)b * (NN * 128);
    const int*   ag = adj + (size_t)b * (NN * NN);

    for (int idx = tid; idx < NN * 32; idx += 256) {
        int i = idx >> 5, c4 = (idx & 31) << 2;
        *reinterpret_cast<float4*>(&S[i * NPAD + c4]) = reinterpret_cast<const float4*>(hg)[idx];
    }
    for (int idx = tid; idx < NN * NN; idx += 256)
        ADJ[(idx >> 6) * 68 + (idx & 63)] = (unsigned char)ag[idx];
    if (tid < 128) {
        A[tid] = a0[tid]; A[128 + tid] = a1[tid];
        A[256 + tid] = a2[tid]; A[384 + tid] = a3[tid];
    }
    if (tid < 64) MS[tid] = mask[b * NN + tid];
    __syncthreads();
    build_tile(S, nullptr, XT, tid);   // persistent X tile
    if (tid < 128) {
        float acc = 0.f, msum = 0.f;
        #pragma unroll 8
        for (int i = 0; i < NN; i++) { acc += S[i * NPAD + tid] * MS[i]; msum += MS[i]; }
        STAR[tid] = acc / msum;
    }
    __syncthreads();

    const float RSQ = 0.088388347648318447f;
    const int mstrip = warp & 3, nhalf = warp >> 2;
    const int R0 = mstrip * 16, N0 = nhalf * 32;
    const int g = lane >> 2, i0 = R0 + g;
    const int lsel = lane & 15;
    const int m4 = lane >> 3;
    const uint32_t abase = XH + (uint32_t)(R0 + (lane & 7) + ((m4 & 1) << 3)) * TS
                         + ((m4 >> 1) << 4);
    const uint32_t bbase = YH + (uint32_t)(N0 + (lsel & 7)) * TS + ((lsel >> 3) << 4);

    // preload adj codes this thread selects on (same for both steps)
    unsigned short adjp[8];
    #pragma unroll
    for (int nt = 0; nt < 4; nt++) {
        int j0 = N0 + nt * 8 + ((lane & 3) << 1);
        adjp[nt * 2]     = *reinterpret_cast<const unsigned short*>(&ADJ[i0 * 68 + j0]);
        adjp[nt * 2 + 1] = *reinterpret_cast<const unsigned short*>(&ADJ[(i0 + 8) * 68 + j0]);
    }

    for (int step = 0; step < 2; step++) {
        // ===== star matvecs (row-major float4, parallel pairs) =====
        {
            const int gg = warp >> 2;
            const int t = tid & 127;
            const float* MT = gg ? g_M2 : g_M1;
            float* V2g = gg ? V2B : V2A;
            const float4* mr = reinterpret_cast<const float4*>(MT + t * 128);
            float acc = 0.f;
            #pragma unroll 8
            for (int d4 = 0; d4 < 32; d4++) {
                float4 mv = __ldg(&mr[d4]);
                float4 sv = *reinterpret_cast<const float4*>(&STAR[d4 * 4]);
                acc += mv.x * sv.x + mv.y * sv.y + mv.z * sv.z + mv.w * sv.w;
            }
            V2g[t] = acc;
        }

        // ===== A frags (X tile, current S) =====
        uint32_t ah[32], al[32];
        #pragma unroll
        for (int kt = 0; kt < 8; kt++) {
            LDSM4(&ah[kt * 4], abase + kt * 32);
            LDSM4(&al[kt * 4], abase + THALF + kt * 32);
        }

        // ===== e-logits: per k build Y, MMA, reg-select =====
        float sel[4][4];
        #pragma unroll
        for (int nt = 0; nt < 4; nt++)
            #pragma unroll
            for (int q = 0; q < 4; q++) sel[nt][q] = NEG_BIG;
        for (int k = 0; k < 4; k++) {
            __syncthreads();                       // prev MMA reads done
            build_tile(S, A + k * 128, YT, tid);
            __syncthreads();
            const unsigned short code2 = (unsigned short)(k + 1);
            #pragma unroll
            for (int nt = 0; nt < 4; nt++) {
                float c0 = 0.f, c1 = 0.f, c2 = 0.f, c3 = 0.f;
                #pragma unroll
                for (int kt = 0; kt < 8; kt++) {
                    uint32_t bh0, bh1, bl0, bl1;
                    uint32_t ba = bbase + nt * (8 * TS) + kt * 32;
                    LDSM2(bh0, bh1, ba);
                    LDSM2(bl0, bl1, ba + THALF);
                    MMA16816(c0, c1, c2, c3, &ah[kt * 4], bh0, bh1);
                    MMA16816(c0, c1, c2, c3, &ah[kt * 4], bl0, bl1);
                    MMA16816(c0, c1, c2, c3, &al[kt * 4], bh0, bh1);
                }
                unsigned short p0 = adjp[nt * 2], p1 = adjp[nt * 2 + 1];
                if ((p0 & 0xFF) == code2)  sel[nt][0] = (c0 >= 0.f) ? c0 : 0.2f * c0;
                if ((p0 >> 8)   == code2)  sel[nt][1] = (c1 >= 0.f) ? c1 : 0.2f * c1;
                if ((p1 & 0xFF) == code2)  sel[nt][2] = (c2 >= 0.f) ? c2 : 0.2f * c2;
                if ((p1 >> 8)   == code2)  sel[nt][3] = (c3 >= 0.f) ? c3 : 0.2f * c3;
            }
        }

        // ===== fragment softmax =====
        float m0 = NEG_BIG, m1 = NEG_BIG;
        #pragma unroll
        for (int nt = 0; nt < 4; nt++) {
            m0 = fmaxf(m0, fmaxf(sel[nt][0], sel[nt][1]));
            m1 = fmaxf(m1, fmaxf(sel[nt][2], sel[nt][3]));
        }
        m0 = fmaxf(m0, __shfl_xor_sync(0xffffffffu, m0, 1));
        m0 = fmaxf(m0, __shfl_xor_sync(0xffffffffu, m0, 2));
        m1 = fmaxf(m1, __shfl_xor_sync(0xffffffffu, m1, 1));
        m1 = fmaxf(m1, __shfl_xor_sync(0xffffffffu, m1, 2));
        if ((lane & 3) == 0) { PA[i0 * 2 + nhalf] = m0; PA[(i0 + 8) * 2 + nhalf] = m1; }
        __syncthreads();
        m0 = fmaxf(PA[i0 * 2], PA[i0 * 2 + 1]);
        m1 = fmaxf(PA[(i0 + 8) * 2], PA[(i0 + 8) * 2 + 1]);
        float s0 = 0.f, s1 = 0.f;
        #pragma unroll
        for (int nt = 0; nt < 4; nt++) {
            sel[nt][0] = __expf(sel[nt][0] - m0); s0 += sel[nt][0];
            sel[nt][1] = __expf(sel[nt][1] - m0); s0 += sel[nt][1];
            sel[nt][2] = __expf(sel[nt][2] - m1); s1 += sel[nt][2];
            sel[nt][3] = __expf(sel[nt][3] - m1); s1 += sel[nt][3];
        }
        s0 += __shfl_xor_sync(0xffffffffu, s0, 1);
        s0 += __shfl_xor_sync(0xffffffffu, s0, 2);
        s1 += __shfl_xor_sync(0xffffffffu, s1, 1);
        s1 += __shfl_xor_sync(0xffffffffu, s1, 2);
        if ((lane & 3) == 0) { PB[i0 * 2 + nhalf] = s0; PB[(i0 + 8) * 2 + nhalf] = s1; }
        __syncthreads();
        float inv0 = 1.f / (PB[i0 * 2] + PB[i0 * 2 + 1]);
        float inv1 = 1.f / (PB[(i0 + 8) * 2] + PB[(i0 + 8) * 2 + 1]);

        // ===== write ATT tile (into Y region, Y dead) =====
        #pragma unroll
        for (int nt = 0; nt < 4; nt++) {
            int j0 = N0 + nt * 8 + ((lane & 3) << 1);
            uint32_t hi, lo;
            cvt_hilo(make_float2(sel[nt][0] * inv0, sel[nt][1] * inv0), hi, lo);
            int off = i0 * ATT_S + j0 * 2;
            *reinterpret_cast<uint32_t*>(YT + off)            = hi;
            *reinterpret_cast<uint32_t*>(YT + ATT_HALF + off) = lo;
            cvt_hilo(make_float2(sel[nt][2] * inv1, sel[nt][3] * inv1), hi, lo);
            off = (i0 + 8) * ATT_S + j0 * 2;
            *reinterpret_cast<uint32_t*>(YT + off)            = hi;
            *reinterpret_cast<uint32_t*>(YT + ATT_HALF + off) = lo;
        }
        __syncthreads();

        // ===== T = att @ S (A from ATT, B = X^T) =====
        {
            uint32_t aah[16], aal[16];
            uint32_t tabase = YH + (uint32_t)(R0 + (lane & 7) + ((m4 & 1) << 3)) * ATT_S
                            + ((m4 >> 1) << 4);
            #pragma unroll
            for (int kt = 0; kt < 4; kt++) {
                LDSM4(&aah[kt * 4], tabase + kt * 32);
                LDSM4(&aal[kt * 4], tabase + ATT_HALF + kt * 32);
            }
            const int N0d = nhalf * 64;
            float tc[8][4];
            #pragma unroll
            for (int nt = 0; nt < 8; nt++)
                #pragma unroll
                for (int q = 0; q < 4; q++) tc[nt][q] = 0.f;
            #pragma unroll
            for (int nt = 0; nt < 8; nt++) {
                #pragma unroll
                for (int kt = 0; kt < 4; kt++) {
                    uint32_t bh0, bh1, bl0, bl1;
                    uint32_t ba = XH + (uint32_t)(kt * 16 + lsel) * TS + (uint32_t)(N0d + nt * 8) * 2;
                    LDSM2T(bh0, bh1, ba);
                    LDSM2T(bl0, bl1, ba + THALF);
                    MMA16816(tc[nt][0], tc[nt][1], tc[nt][2], tc[nt][3], &aah[kt * 4], bh0, bh1);
                    MMA16816(tc[nt][0], tc[nt][1], tc[nt][2], tc[nt][3], &aah[kt * 4], bl0, bl1);
                    MMA16816(tc[nt][0], tc[nt][1], tc[nt][2], tc[nt][3], &aal[kt * 4], bh0, bh1);
                }
            }

            float pa0 = 0.f, pa1 = 0.f;
            #pragma unroll
            for (int nt = 0; nt < 8; nt++) {
                int d0 = N0d + nt * 8 + ((lane & 3) << 1);
                float2 va = *reinterpret_cast<const float2*>(&V2A[d0]);
                pa0 += tc[nt][0] * va.x + tc[nt][1] * va.y;
                pa1 += tc[nt][2] * va.x + tc[nt][3] * va.y;
            }
            pa0 += __shfl_xor_sync(0xffffffffu, pa0, 1);
            pa0 += __shfl_xor_sync(0xffffffffu, pa0, 2);
            pa1 += __shfl_xor_sync(0xffffffffu, pa1, 1);
            pa1 += __shfl_xor_sync(0xffffffffu, pa1, 2);
            if ((lane & 3) == 0) { PA[i0 * 2 + nhalf] = pa0; PA[(i0 + 8) * 2 + nhalf] = pa1; }
            __syncthreads();    // PA exchange + guards X writes below vs X reads above
            float al0 = (PA[i0 * 2] + PA[i0 * 2 + 1]) * RSQ;
            float al1 = (PA[(i0 + 8) * 2] + PA[(i0 + 8) * 2 + 1]) * RSQ;

            float pb0 = 0.f, pb1 = 0.f;
            #pragma unroll
            for (int nt = 0; nt < 8; nt++) {
                int d0 = N0d + nt * 8 + ((lane & 3) << 1);
                float2 st = *reinterpret_cast<const float2*>(&STAR[d0]);
                float2 vb = *reinterpret_cast<const float2*>(&V2B[d0]);
                float n0x = (1.f - al0) * tc[nt][0] + al0 * st.x;
                float n0y = (1.f - al0) * tc[nt][1] + al0 * st.y;
                float n1x = (1.f - al1) * tc[nt][2] + al1 * st.x;
                float n1y = (1.f - al1) * tc[nt][3] + al1 * st.y;
                *reinterpret_cast<float2*>(&S[i0 * NPAD + d0])       = make_float2(n0x, n0y);
                *reinterpret_cast<float2*>(&S[(i0 + 8) * NPAD + d0]) = make_float2(n1x, n1y);
                uint32_t hi, lo;
                int off = i0 * TS + d0 * 2;
                cvt_hilo(make_float2(n0x, n0y), hi, lo);
                *reinterpret_cast<uint32_t*>(XT + off)         = hi;
                *reinterpret_cast<uint32_t*>(XT + THALF + off) = lo;
                off = (i0 + 8) * TS + d0 * 2;
                cvt_hilo(make_float2(n1x, n1y), hi, lo);
                *reinterpret_cast<uint32_t*>(XT + off)         = hi;
                *reinterpret_cast<uint32_t*>(XT + THALF + off) = lo;
                pb0 += n0x * vb.x + n0y * vb.y;
                pb1 += n1x * vb.x + n1y * vb.y;
            }
            pb0 += __shfl_xor_sync(0xffffffffu, pb0, 1);
            pb0 += __shfl_xor_sync(0xffffffffu, pb0, 2);
            pb1 += __shfl_xor_sync(0xffffffffu, pb1, 1);
            pb1 += __shfl_xor_sync(0xffffffffu, pb1, 2);
            if ((lane & 3) == 0) { PB[i0 * 2 + nhalf] = pb0; PB[(i0 + 8) * 2 + nhalf] = pb1; }
        }
        __syncthreads();

        if (warp == 0) {
            float b0 = (MS[lane] == 0.f)      ? __int_as_float(0xff800000)
                                              : (PB[lane * 2] + PB[lane * 2 + 1]) * RSQ;
            float b1 = (MS[lane + 32] == 0.f) ? __int_as_float(0xff800000)
                                              : (PB[(lane + 32) * 2] + PB[(lane + 32) * 2 + 1]) * RSQ;
            float m = fmaxf(b0, b1);
            #pragma unroll
            for (int o = 16; o > 0; o >>= 1) m = fmaxf(m, __shfl_xor_sync(0xffffffffu, m, o));
            float e0 = __expf(b0 - m), e1 = __expf(b1 - m);
            float sE = e0 + e1;
            #pragma unroll
            for (int o = 16; o > 0; o >>= 1) sE += __shfl_xor_sync(0xffffffffu, sE, o);
            float inv = 1.f / sE;
            BR[lane] = e0 * inv; BR[lane + 32] = e1 * inv;
        }
        __syncthreads();
        if (tid < 128) {
            float acc = 0.f;
            #pragma unroll 8
            for (int j = 0; j < 64; j++) acc += BR[j] * S[j * NPAD + tid];
            STAR[tid] = acc;
        }
        __syncthreads();
    }

    // ===== gate: C = cat(hidden,S) @ W^T =====
    {
        char* WT = YT;
        const uint32_t WTH = YH;
        const int N0g = nhalf * 64;
        float acc[8][4];
        #pragma unroll
        for (int nt = 0; nt < 8; nt++)
            #pragma unroll
            for (int q = 0; q < 4; q++) acc[nt][q] = 0.f;

        for (int chunk = 0; chunk < 4; chunk++) {
            const int c0 = chunk * 64;
            __syncthreads();
            for (int idx = tid; idx < 2048; idx += 256) {
                int o = idx >> 4, p4 = idx & 15;
                float4 w = __ldg(reinterpret_cast<const float4*>(&wlin[o * 256 + c0 + p4 * 4]));
                uint32_t h0, l0, h1, l1;
                cvt_hilo(make_float2(w.x, w.y), h0, l0);
                cvt_hilo(make_float2(w.z, w.w), h1, l1);
                *reinterpret_cast<uint2*>(WT + o * GWS + p4 * 8)          = make_uint2(h0, h1);
                *reinterpret_cast<uint2*>(WT + GWHALF + o * GWS + p4 * 8) = make_uint2(l0, l1);
            }
            __syncthreads();
            const bool fh2 = chunk < 2;
            const int cb = fh2 ? c0 : (c0 - 128);
            const int r0 = i0;
            #pragma unroll
            for (int kt = 0; kt < 4; kt++) {
                uint32_t fah[4], fal[4];
                if (fh2) {
                    int cc = cb + kt * 16 + ((lane & 3) << 1);
                    float2 x00 = __ldg(reinterpret_cast<const float2*>(&hg[r0 * 128 + cc]));
                    float2 x10 = __ldg(reinterpret_cast<const float2*>(&hg[(r0 + 8) * 128 + cc]));
                    float2 x01 = __ldg(reinterpret_cast<const float2*>(&hg[r0 * 128 + cc + 8]));
                    float2 x11 = __ldg(reinterpret_cast<const float2*>(&hg[(r0 + 8) * 128 + cc + 8]));
                    cvt_hilo(x00, fah[0], fal[0]);
                    cvt_hilo(x10, fah[1], fal[1]);
                    cvt_hilo(x01, fah[2], fal[2]);
                    cvt_hilo(x11, fah[3], fal[3]);
                } else {
                    uint32_t ab2 = abase + (uint32_t)(cb + kt * 16) * 2;
                    LDSM4(fah, ab2);
                    LDSM4(fal, ab2 + THALF);
                }
                uint32_t bb = WTH + (uint32_t)(N0g + (lsel & 7)) * GWS + ((lsel >> 3) << 4) + kt * 32;
                #pragma unroll
                for (int nt = 0; nt < 8; nt++) {
                    uint32_t bh0, bh1, bl0, bl1;
                    uint32_t ba = bb + nt * (8 * GWS);
                    LDSM2(bh0, bh1, ba);
                    LDSM2(bl0, bl1, ba + GWHALF);
                    MMA16816(acc[nt][0], acc[nt][1], acc[nt][2], acc[nt][3], fah, bh0, bh1);
                    MMA16816(acc[nt][0], acc[nt][1], acc[nt][2], acc[nt][3], fah, bl0, bl1);
                    MMA16816(acc[nt][0], acc[nt][1], acc[nt][2], acc[nt][3], fal, bh0, bh1);
                }
            }
        }

        float* ob = outp + (size_t)b * (NN * 128);
        const int r0 = i0;
        #pragma unroll
        for (int nt = 0; nt < 8; nt++) {
            int o0 = N0g + nt * 8 + ((lane & 3) << 1);
            float2 h0 = __ldg(reinterpret_cast<const float2*>(&hg[r0 * 128 + o0]));
            float2 s0v = *reinterpret_cast<const float2*>(&S[r0 * NPAD + o0]);
            float2 h1 = __ldg(reinterpret_cast<const float2*>(&hg[(r0 + 8) * 128 + o0]));
            float2 s1v = *reinterpret_cast<const float2*>(&S[(r0 + 8) * NPAD + o0]);
            float g00 = 1.f / (1.f + __expf(-acc[nt][0]));
            float g01 = 1.f / (1.f + __expf(-acc[nt][1]));
            float g10 = 1.f / (1.f + __expf(-acc[nt][2]));
            float g11 = 1.f / (1.f + __expf(-acc[nt][3]));
            float2 r0v, r1v;
            r0v.x = g00 * h0.x + (1.f - g00) * s0v.x;
            r0v.y = g01 * h0.y + (1.f - g01) * s0v.y;
            r1v.x = g10 * h1.x + (1.f - g10) * s1v.x;
            r1v.y = g11 * h1.y + (1.f - g11) * s1v.y;
            *reinterpret_cast<float2*>(&ob[r0 * 128 + o0])       = r0v;
            *reinterpret_cast<float2*>(&ob[(r0 + 8) * 128 + o0]) = r1v;
        }
    }
    if (tid < 128) starp[(size_t)b * 128 + tid] = STAR[tid];
}

extern "C" void kernel_launch(void* const* d_in, const int* in_sizes, int n_in,
                              void* d_out, int out_size) {
    float* outp  = (float*)d_out;
    float* starp = outp + (size_t)NB * NN * 128;

    prep_kernel<<<128, 256>>>((const float*)d_in[7], (const float*)d_in[8],
                              (const float*)d_in[9], (const float*)d_in[10]);
    cudaFuncSetAttribute(star_agg_kernel, cudaFuncAttributeMaxDynamicSharedMemorySize, SM_BYTES);
    star_agg_kernel<<<NB, 256, SM_BYTES>>>(
        (const float*)d_in[0], (const int*)d_in[1], (const float*)d_in[2],
        (const float*)d_in[3], (const float*)d_in[4], (const float*)d_in[5], (const float*)d_in[6],
        (const float*)d_in[11], outp, starp);
}

// round 13
// speedup vs baseline: 1.2768x; 1.2202x over previous
#include <cuda_runtime.h>
#include <cuda_bf16.h>
#include <cstdint>

#define NB   2048
#define NN   64
#define NPAD 132
#define NEG_BIG (-9000000000000000.0f)

#define OFF_S    0          // 64*132 fp32
#define OFF_X    8448       // persistent S bf16 hi/lo tile (34816B)
#define OFF_Y    17152      // Y_k tile | ATT tile | gate W staging
#define OFF_A    25856      // a_k
#define OFF_STAR 26368
#define OFF_V2A  26496
#define OFF_V2B  26624
#define OFF_MS   26752
#define OFF_BR   26816
#define OFF_PA   26880
#define OFF_PB   27008
#define SM_FLOATS 27136
#define SM_BYTES (SM_FLOATS*4 + 64*68)

#define TS    272
#define THALF 17408
#define ATT_S 144
#define ATT_HALF 9216
#define GWS   144
#define GWHALF (128*144)

__device__ float g_M1T[16384];   // (q1 @ k1^T)^T — coalesced column access
__device__ float g_M2T[16384];   // (k2 @ q2^T)^T

__device__ __forceinline__ uint32_t smem_u32(const void* p) {
    uint32_t a;
    asm("{ .reg .u64 t; cvta.to.shared.u64 t, %1; cvt.u32.u64 %0, t; }" : "=r"(a) : "l"(p));
    return a;
}
__device__ __forceinline__ uint32_t pack_bf2(__nv_bfloat16 a, __nv_bfloat16 b) {
    __nv_bfloat162 v = __halves2bfloat162(a, b);
    return *reinterpret_cast<uint32_t*>(&v);
}
__device__ __forceinline__ void cvt_hilo(float2 v, uint32_t& hi, uint32_t& lo) {
    __nv_bfloat16 h0 = __float2bfloat16_rn(v.x), h1 = __float2bfloat16_rn(v.y);
    hi = pack_bf2(h0, h1);
    lo = pack_bf2(__float2bfloat16_rn(v.x - __bfloat162float(h0)),
                  __float2bfloat16_rn(v.y - __bfloat162float(h1)));
}

#define LDSM4(r, addr) \
    asm volatile("ldmatrix.sync.aligned.m8n8.x4.shared.b16 {%0,%1,%2,%3}, [%4];" \
        : "=r"((r)[0]), "=r"((r)[1]), "=r"((r)[2]), "=r"((r)[3]) : "r"(addr))
#define LDSM2(r0, r1, addr) \
    asm volatile("ldmatrix.sync.aligned.m8n8.x2.shared.b16 {%0,%1}, [%2];" \
        : "=r"(r0), "=r"(r1) : "r"(addr))
#define LDSM2T(r0, r1, addr) \
    asm volatile("ldmatrix.sync.aligned.m8n8.x2.trans.shared.b16 {%0,%1}, [%2];" \
        : "=r"(r0), "=r"(r1) : "r"(addr))
#define MMA16816(c0,c1,c2,c3, a, b0,b1) \
    asm volatile("mma.sync.aligned.m16n8k16.row.col.f32.bf16.bf16.f32 " \
        "{%0,%1,%2,%3}, {%4,%5,%6,%7}, {%8,%9}, {%0,%1,%2,%3};" \
        : "+f"(c0), "+f"(c1), "+f"(c2), "+f"(c3) \
        : "r"((a)[0]), "r"((a)[1]), "r"((a)[2]), "r"((a)[3]), "r"(b0), "r"(b1))

__device__ __forceinline__ void build_tile(const float* S, const float* vec,
                                           char* tile, int tid) {
    for (int p = tid; p < 4096; p += 256) {
        int row = p >> 6, d = (p & 63) << 1;
        float2 sv = *reinterpret_cast<const float2*>(&S[row * NPAD + d]);
        float x0 = sv.x, x1 = sv.y;
        if (vec) { x0 *= vec[d]; x1 *= vec[d + 1]; }
        uint32_t hi, lo;
        cvt_hilo(make_float2(x0, x1), hi, lo);
        int off = row * TS + d * 2;
        *reinterpret_cast<uint32_t*>(tile + off)         = hi;
        *reinterpret_cast<uint32_t*>(tile + THALF + off) = lo;
    }
}

__global__ void prep_kernel(const float* __restrict__ q1, const float* __restrict__ k1,
                            const float* __restrict__ q2, const float* __restrict__ k2) {
    int o = blockIdx.x * 256 + threadIdx.x;
    int m = o >> 14, idx = o & 16383;
    int t = idx >> 7, c = idx & 127;
    const float* X = m ? k2 : q1;
    const float* Y = m ? q2 : k1;
    float acc = 0.f;
    const float4* xr = reinterpret_cast<const float4*>(X + t * 128);
    const float4* yr = reinterpret_cast<const float4*>(Y + c * 128);
    #pragma unroll 8
    for (int d = 0; d < 32; d++) {
        float4 xv = xr[d], yv = yr[d];
        acc += xv.x * yv.x + xv.y * yv.y + xv.z * yv.z + xv.w * yv.w;
    }
    (m ? g_M2T : g_M1T)[c * 128 + t] = acc;   // transposed for coalesced access
}

__global__ void __launch_bounds__(256, 2)
star_agg_kernel(const float* __restrict__ hidden, const int* __restrict__ adj,
                const float* __restrict__ mask,
                const float* __restrict__ a0, const float* __restrict__ a1,
                const float* __restrict__ a2, const float* __restrict__ a3,
                const float* __restrict__ wlin,
                float* __restrict__ outp, float* __restrict__ starp)
{
    extern __shared__ float sm[];
    float* S    = sm + OFF_S;
    float* A    = sm + OFF_A;
    float* STAR = sm + OFF_STAR;
    float* V2A  = sm + OFF_V2A;
    float* V2B  = sm + OFF_V2B;
    float* MS   = sm + OFF_MS;
    float* BR   = sm + OFF_BR;
    float* PA   = sm + OFF_PA;
    float* PB   = sm + OFF_PB;
    char*  XT   = (char*)(sm + OFF_X);
    char*  YT   = (char*)(sm + OFF_Y);
    unsigned char* ADJ = (unsigned char*)(sm + SM_FLOATS);  // [i][j] stride 68

    const int tid = threadIdx.x, lane = tid & 31, warp = tid >> 5, b = blockIdx.x;
    const uint32_t smb = smem_u32(sm);
    const uint32_t XH = smb + OFF_X * 4;
    const uint32_t YH = smb + OFF_Y * 4;
    const float* hg = hidden + (size_t)b * (NN * 128);
    const int*   ag = adj + (size_t)b * (NN * NN);

    for (int idx = tid; idx < NN * 32; idx += 256) {
        int i = idx >> 5, c4 = (idx & 31) << 2;
        *reinterpret_cast<float4*>(&S[i * NPAD + c4]) = reinterpret_cast<const float4*>(hg)[idx];
    }
    for (int idx = tid; idx < NN * NN; idx += 256)
        ADJ[(idx >> 6) * 68 + (idx & 63)] = (unsigned char)ag[idx];
    if (tid < 128) {
        A[tid] = a0[tid]; A[128 + tid] = a1[tid];
        A[256 + tid] = a2[tid]; A[384 + tid] = a3[tid];
    }
    if (tid < 64) MS[tid] = mask[b * NN + tid];
    __syncthreads();
    build_tile(S, nullptr, XT, tid);   // persistent X tile
    if (tid < 128) {
        float acc = 0.f, msum = 0.f;
        #pragma unroll 8
        for (int i = 0; i < NN; i++) { acc += S[i * NPAD + tid] * MS[i]; msum += MS[i]; }
        STAR[tid] = acc / msum;
    }
    __syncthreads();

    const float RSQ = 0.088388347648318447f;
    const int mstrip = warp & 3, nhalf = warp >> 2;
    const int R0 = mstrip * 16, N0 = nhalf * 32;
    const int g = lane >> 2, i0 = R0 + g;
    const int lsel = lane & 15;
    const int m4 = lane >> 3;
    const uint32_t abase = XH + (uint32_t)(R0 + (lane & 7) + ((m4 & 1) << 3)) * TS
                         + ((m4 >> 1) << 4);
    const uint32_t bbase = YH + (uint32_t)(N0 + (lsel & 7)) * TS + ((lsel >> 3) << 4);

    // preload adj codes this thread selects on (same for both steps)
    unsigned short adjp[8];
    #pragma unroll
    for (int nt = 0; nt < 4; nt++) {
        int j0 = N0 + nt * 8 + ((lane & 3) << 1);
        adjp[nt * 2]     = *reinterpret_cast<const unsigned short*>(&ADJ[i0 * 68 + j0]);
        adjp[nt * 2 + 1] = *reinterpret_cast<const unsigned short*>(&ADJ[(i0 + 8) * 68 + j0]);
    }

    for (int step = 0; step < 2; step++) {
        // ===== star matvecs (coalesced transposed layout, parallel pairs) =====
        {
            const int gg = warp >> 2;
            const int t = tid & 127;
            const float* MT = gg ? g_M2T : g_M1T;
            float* V2g = gg ? V2B : V2A;
            float s0 = 0.f, s1 = 0.f, s2 = 0.f, s3 = 0.f;
            #pragma unroll 8
            for (int c = 0; c < 128; c += 4) {
                s0 += STAR[c]     * MT[c * 128 + t];
                s1 += STAR[c + 1] * MT[(c + 1) * 128 + t];
                s2 += STAR[c + 2] * MT[(c + 2) * 128 + t];
                s3 += STAR[c + 3] * MT[(c + 3) * 128 + t];
            }
            V2g[t] = (s0 + s1) + (s2 + s3);
        }

        // ===== A frags (X tile, current S) =====
        uint32_t ah[32], al[32];
        #pragma unroll
        for (int kt = 0; kt < 8; kt++) {
            LDSM4(&ah[kt * 4], abase + kt * 32);
            LDSM4(&al[kt * 4], abase + THALF + kt * 32);
        }

        // ===== e-logits: per k build Y, MMA, reg-select =====
        float sel[4][4];
        #pragma unroll
        for (int nt = 0; nt < 4; nt++)
            #pragma unroll
            for (int q = 0; q < 4; q++) sel[nt][q] = NEG_BIG;
        for (int k = 0; k < 4; k++) {
            __syncthreads();                       // prev MMA reads done
            build_tile(S, A + k * 128, YT, tid);
            __syncthreads();
            const unsigned short code2 = (unsigned short)(k + 1);
            #pragma unroll
            for (int nt = 0; nt < 4; nt++) {
                float c0 = 0.f, c1 = 0.f, c2 = 0.f, c3 = 0.f;
                #pragma unroll
                for (int kt = 0; kt < 8; kt++) {
                    uint32_t bh0, bh1, bl0, bl1;
                    uint32_t ba = bbase + nt * (8 * TS) + kt * 32;
                    LDSM2(bh0, bh1, ba);
                    LDSM2(bl0, bl1, ba + THALF);
                    MMA16816(c0, c1, c2, c3, &ah[kt * 4], bh0, bh1);
                    MMA16816(c0, c1, c2, c3, &ah[kt * 4], bl0, bl1);
                    MMA16816(c0, c1, c2, c3, &al[kt * 4], bh0, bh1);
                }
                unsigned short p0 = adjp[nt * 2], p1 = adjp[nt * 2 + 1];
                if ((p0 & 0xFF) == code2)  sel[nt][0] = (c0 >= 0.f) ? c0 : 0.2f * c0;
                if ((p0 >> 8)   == code2)  sel[nt][1] = (c1 >= 0.f) ? c1 : 0.2f * c1;
                if ((p1 & 0xFF) == code2)  sel[nt][2] = (c2 >= 0.f) ? c2 : 0.2f * c2;
                if ((p1 >> 8)   == code2)  sel[nt][3] = (c3 >= 0.f) ? c3 : 0.2f * c3;
            }
        }

        // ===== fragment softmax =====
        float m0 = NEG_BIG, m1 = NEG_BIG;
        #pragma unroll
        for (int nt = 0; nt < 4; nt++) {
            m0 = fmaxf(m0, fmaxf(sel[nt][0], sel[nt][1]));
            m1 = fmaxf(m1, fmaxf(sel[nt][2], sel[nt][3]));
        }
        m0 = fmaxf(m0, __shfl_xor_sync(0xffffffffu, m0, 1));
        m0 = fmaxf(m0, __shfl_xor_sync(0xffffffffu, m0, 2));
        m1 = fmaxf(m1, __shfl_xor_sync(0xffffffffu, m1, 1));
        m1 = fmaxf(m1, __shfl_xor_sync(0xffffffffu, m1, 2));
        if ((lane & 3) == 0) { PA[i0 * 2 + nhalf] = m0; PA[(i0 + 8) * 2 + nhalf] = m1; }
        __syncthreads();
        m0 = fmaxf(PA[i0 * 2], PA[i0 * 2 + 1]);
        m1 = fmaxf(PA[(i0 + 8) * 2], PA[(i0 + 8) * 2 + 1]);
        float s0 = 0.f, s1 = 0.f;
        #pragma unroll
        for (int nt = 0; nt < 4; nt++) {
            sel[nt][0] = __expf(sel[nt][0] - m0); s0 += sel[nt][0];
            sel[nt][1] = __expf(sel[nt][1] - m0); s0 += sel[nt][1];
            sel[nt][2] = __expf(sel[nt][2] - m1); s1 += sel[nt][2];
            sel[nt][3] = __expf(sel[nt][3] - m1); s1 += sel[nt][3];
        }
        s0 += __shfl_xor_sync(0xffffffffu, s0, 1);
        s0 += __shfl_xor_sync(0xffffffffu, s0, 2);
        s1 += __shfl_xor_sync(0xffffffffu, s1, 1);
        s1 += __shfl_xor_sync(0xffffffffu, s1, 2);
        if ((lane & 3) == 0) { PB[i0 * 2 + nhalf] = s0; PB[(i0 + 8) * 2 + nhalf] = s1; }
        __syncthreads();
        float inv0 = 1.f / (PB[i0 * 2] + PB[i0 * 2 + 1]);
        float inv1 = 1.f / (PB[(i0 + 8) * 2] + PB[(i0 + 8) * 2 + 1]);

        // ===== write ATT tile (into Y region, Y dead) =====
        #pragma unroll
        for (int nt = 0; nt < 4; nt++) {
            int j0 = N0 + nt * 8 + ((lane & 3) << 1);
            uint32_t hi, lo;
            cvt_hilo(make_float2(sel[nt][0] * inv0, sel[nt][1] * inv0), hi, lo);
            int off = i0 * ATT_S + j0 * 2;
            *reinterpret_cast<uint32_t*>(YT + off)            = hi;
            *reinterpret_cast<uint32_t*>(YT + ATT_HALF + off) = lo;
            cvt_hilo(make_float2(sel[nt][2] * inv1, sel[nt][3] * inv1), hi, lo);
            off = (i0 + 8) * ATT_S + j0 * 2;
            *reinterpret_cast<uint32_t*>(YT + off)            = hi;
            *reinterpret_cast<uint32_t*>(YT + ATT_HALF + off) = lo;
        }
        __syncthreads();

        // ===== T = att @ S (A from ATT, B = X^T) =====
        {
            uint32_t aah[16], aal[16];
            uint32_t tabase = YH + (uint32_t)(R0 + (lane & 7) + ((m4 & 1) << 3)) * ATT_S
                            + ((m4 >> 1) << 4);
            #pragma unroll
            for (int kt = 0; kt < 4; kt++) {
                LDSM4(&aah[kt * 4], tabase + kt * 32);
                LDSM4(&aal[kt * 4], tabase + ATT_HALF + kt * 32);
            }
            const int N0d = nhalf * 64;
            float tc[8][4];
            #pragma unroll
            for (int nt = 0; nt < 8; nt++)
                #pragma unroll
                for (int q = 0; q < 4; q++) tc[nt][q] = 0.f;
            #pragma unroll
            for (int nt = 0; nt < 8; nt++) {
                #pragma unroll
                for (int kt = 0; kt < 4; kt++) {
                    uint32_t bh0, bh1, bl0, bl1;
                    uint32_t ba = XH + (uint32_t)(kt * 16 + lsel) * TS + (uint32_t)(N0d + nt * 8) * 2;
                    LDSM2T(bh0, bh1, ba);
                    LDSM2T(bl0, bl1, ba + THALF);
                    MMA16816(tc[nt][0], tc[nt][1], tc[nt][2], tc[nt][3], &aah[kt * 4], bh0, bh1);
                    MMA16816(tc[nt][0], tc[nt][1], tc[nt][2], tc[nt][3], &aah[kt * 4], bl0, bl1);
                    MMA16816(tc[nt][0], tc[nt][1], tc[nt][2], tc[nt][3], &aal[kt * 4], bh0, bh1);
                }
            }

            float pa0 = 0.f, pa1 = 0.f;
            #pragma unroll
            for (int nt = 0; nt < 8; nt++) {
                int d0 = N0d + nt * 8 + ((lane & 3) << 1);
                float2 va = *reinterpret_cast<const float2*>(&V2A[d0]);
                pa0 += tc[nt][0] * va.x + tc[nt][1] * va.y;
                pa1 += tc[nt][2] * va.x + tc[nt][3] * va.y;
            }
            pa0 += __shfl_xor_sync(0xffffffffu, pa0, 1);
            pa0 += __shfl_xor_sync(0xffffffffu, pa0, 2);
            pa1 += __shfl_xor_sync(0xffffffffu, pa1, 1);
            pa1 += __shfl_xor_sync(0xffffffffu, pa1, 2);
            if ((lane & 3) == 0) { PA[i0 * 2 + nhalf] = pa0; PA[(i0 + 8) * 2 + nhalf] = pa1; }
            __syncthreads();    // PA exchange + guards X writes below vs X reads above
            float al0 = (PA[i0 * 2] + PA[i0 * 2 + 1]) * RSQ;
            float al1 = (PA[(i0 + 8) * 2] + PA[(i0 + 8) * 2 + 1]) * RSQ;

            float pb0 = 0.f, pb1 = 0.f;
            #pragma unroll
            for (int nt = 0; nt < 8; nt++) {
                int d0 = N0d + nt * 8 + ((lane & 3) << 1);
                float2 st = *reinterpret_cast<const float2*>(&STAR[d0]);
                float2 vb = *reinterpret_cast<const float2*>(&V2B[d0]);
                float n0x = (1.f - al0) * tc[nt][0] + al0 * st.x;
                float n0y = (1.f - al0) * tc[nt][1] + al0 * st.y;
                float n1x = (1.f - al1) * tc[nt][2] + al1 * st.x;
                float n1y = (1.f - al1) * tc[nt][3] + al1 * st.y;
                *reinterpret_cast<float2*>(&S[i0 * NPAD + d0])       = make_float2(n0x, n0y);
                *reinterpret_cast<float2*>(&S[(i0 + 8) * NPAD + d0]) = make_float2(n1x, n1y);
                uint32_t hi, lo;
                int off = i0 * TS + d0 * 2;
                cvt_hilo(make_float2(n0x, n0y), hi, lo);
                *reinterpret_cast<uint32_t*>(XT + off)         = hi;
                *reinterpret_cast<uint32_t*>(XT + THALF + off) = lo;
                off = (i0 + 8) * TS + d0 * 2;
                cvt_hilo(make_float2(n1x, n1y), hi, lo);
                *reinterpret_cast<uint32_t*>(XT + off)         = hi;
                *reinterpret_cast<uint32_t*>(XT + THALF + off) = lo;
                pb0 += n0x * vb.x + n0y * vb.y;
                pb1 += n1x * vb.x + n1y * vb.y;
            }
            pb0 += __shfl_xor_sync(0xffffffffu, pb0, 1);
            pb0 += __shfl_xor_sync(0xffffffffu, pb0, 2);
            pb1 += __shfl_xor_sync(0xffffffffu, pb1, 1);
            pb1 += __shfl_xor_sync(0xffffffffu, pb1, 2);
            if ((lane & 3) == 0) { PB[i0 * 2 + nhalf] = pb0; PB[(i0 + 8) * 2 + nhalf] = pb1; }
        }
        __syncthreads();

        if (warp == 0) {
            float b0 = (MS[lane] == 0.f)      ? __int_as_float(0xff800000)
                                              : (PB[lane * 2] + PB[lane * 2 + 1]) * RSQ;
            float b1 = (MS[lane + 32] == 0.f) ? __int_as_float(0xff800000)
                                              : (PB[(lane + 32) * 2] + PB[(lane + 32) * 2 + 1]) * RSQ;
            float m = fmaxf(b0, b1);
            #pragma unroll
            for (int o = 16; o > 0; o >>= 1) m = fmaxf(m, __shfl_xor_sync(0xffffffffu, m, o));
            float e0 = __expf(b0 - m), e1 = __expf(b1 - m);
            float sE = e0 + e1;
            #pragma unroll
            for (int o = 16; o > 0; o >>= 1) sE += __shfl_xor_sync(0xffffffffu, sE, o);
            float inv = 1.f / sE;
            BR[lane] = e0 * inv; BR[lane + 32] = e1 * inv;
        }
        __syncthreads();
        if (tid < 128) {
            float acc = 0.f;
            #pragma unroll 8
            for (int j = 0; j < 64; j++) acc += BR[j] * S[j * NPAD + tid];
            STAR[tid] = acc;
        }
        __syncthreads();
    }

    // ===== gate: C = cat(hidden,S) @ W^T =====
    {
        char* WT = YT;
        const uint32_t WTH = YH;
        const int N0g = nhalf * 64;
        float acc[8][4];
        #pragma unroll
        for (int nt = 0; nt < 8; nt++)
            #pragma unroll
            for (int q = 0; q < 4; q++) acc[nt][q] = 0.f;

        for (int chunk = 0; chunk < 4; chunk++) {
            const int c0 = chunk * 64;
            __syncthreads();
            for (int idx = tid; idx < 2048; idx += 256) {
                int o = idx >> 4, p4 = idx & 15;
                float4 w = __ldg(reinterpret_cast<const float4*>(&wlin[o * 256 + c0 + p4 * 4]));
                uint32_t h0, l0, h1, l1;
                cvt_hilo(make_float2(w.x, w.y), h0, l0);
                cvt_hilo(make_float2(w.z, w.w), h1, l1);
                *reinterpret_cast<uint2*>(WT + o * GWS + p4 * 8)          = make_uint2(h0, h1);
                *reinterpret_cast<uint2*>(WT + GWHALF + o * GWS + p4 * 8) = make_uint2(l0, l1);
            }
            __syncthreads();
            const bool fh2 = chunk < 2;
            const int cb = fh2 ? c0 : (c0 - 128);
            const int r0 = i0;
            #pragma unroll
            for (int kt = 0; kt < 4; kt++) {
                uint32_t fah[4], fal[4];
                if (fh2) {
                    int cc = cb + kt * 16 + ((lane & 3) << 1);
                    float2 x00 = __ldg(reinterpret_cast<const float2*>(&hg[r0 * 128 + cc]));
                    float2 x10 = __ldg(reinterpret_cast<const float2*>(&hg[(r0 + 8) * 128 + cc]));
                    float2 x01 = __ldg(reinterpret_cast<const float2*>(&hg[r0 * 128 + cc + 8]));
                    float2 x11 = __ldg(reinterpret_cast<const float2*>(&hg[(r0 + 8) * 128 + cc + 8]));
                    cvt_hilo(x00, fah[0], fal[0]);
                    cvt_hilo(x10, fah[1], fal[1]);
                    cvt_hilo(x01, fah[2], fal[2]);
                    cvt_hilo(x11, fah[3], fal[3]);
                } else {
                    uint32_t ab2 = abase + (uint32_t)(cb + kt * 16) * 2;
                    LDSM4(fah, ab2);
                    LDSM4(fal, ab2 + THALF);
                }
                uint32_t bb = WTH + (uint32_t)(N0g + (lsel & 7)) * GWS + ((lsel >> 3) << 4) + kt * 32;
                #pragma unroll
                for (int nt = 0; nt < 8; nt++) {
                    uint32_t bh0, bh1, bl0, bl1;
                    uint32_t ba = bb + nt * (8 * GWS);
                    LDSM2(bh0, bh1, ba);
                    LDSM2(bl0, bl1, ba + GWHALF);
                    MMA16816(acc[nt][0], acc[nt][1], acc[nt][2], acc[nt][3], fah, bh0, bh1);
                    MMA16816(acc[nt][0], acc[nt][1], acc[nt][2], acc[nt][3], fah, bl0, bl1);
                    MMA16816(acc[nt][0], acc[nt][1], acc[nt][2], acc[nt][3], fal, bh0, bh1);
                }
            }
        }

        float* ob = outp + (size_t)b * (NN * 128);
        const int r0 = i0;
        #pragma unroll
        for (int nt = 0; nt < 8; nt++) {
            int o0 = N0g + nt * 8 + ((lane & 3) << 1);
            float2 h0 = __ldg(reinterpret_cast<const float2*>(&hg[r0 * 128 + o0]));
            float2 s0v = *reinterpret_cast<const float2*>(&S[r0 * NPAD + o0]);
            float2 h1 = __ldg(reinterpret_cast<const float2*>(&hg[(r0 + 8) * 128 + o0]));
            float2 s1v = *reinterpret_cast<const float2*>(&S[(r0 + 8) * NPAD + o0]);
            float g00 = 1.f / (1.f + __expf(-acc[nt][0]));
            float g01 = 1.f / (1.f + __expf(-acc[nt][1]));
            float g10 = 1.f / (1.f + __expf(-acc[nt][2]));
            float g11 = 1.f / (1.f + __expf(-acc[nt][3]));
            float2 r0v, r1v;
            r0v.x = g00 * h0.x + (1.f - g00) * s0v.x;
            r0v.y = g01 * h0.y + (1.f - g01) * s0v.y;
            r1v.x = g10 * h1.x + (1.f - g10) * s1v.x;
            r1v.y = g11 * h1.y + (1.f - g11) * s1v.y;
            *reinterpret_cast<float2*>(&ob[r0 * 128 + o0])       = r0v;
            *reinterpret_cast<float2*>(&ob[(r0 + 8) * 128 + o0]) = r1v;
        }
    }
    if (tid < 128) starp[(size_t)b * 128 + tid] = STAR[tid];
}

extern "C" void kernel_launch(void* const* d_in, const int* in_sizes, int n_in,
                              void* d_out, int out_size) {
    float* outp  = (float*)d_out;
    float* starp = outp + (size_t)NB * NN * 128;

    prep_kernel<<<128, 256>>>((const float*)d_in[7], (const float*)d_in[8],
                              (const float*)d_in[9], (const float*)d_in[10]);
    cudaFuncSetAttribute(star_agg_kernel, cudaFuncAttributeMaxDynamicSharedMemorySize, SM_BYTES);
    star_agg_kernel<<<NB, 256, SM_BYTES>>>(
        (const float*)d_in[0], (const int*)d_in[1], (const float*)d_in[2],
        (const float*)d_in[3], (const float*)d_in[4], (const float*)d_in[5], (const float*)d_in[6],
        (const float*)d_in[11], outp, starp);
}

// round 14
// speedup vs baseline: 1.2806x; 1.0030x over previous
#include <cuda_runtime.h>
#include <cuda_bf16.h>
#include <cstdint>

#define NB   2048
#define NN   64
#define NPAD 132
#define NEG_BIG (-9000000000000000.0f)

#define OFF_S    0
#define OFF_X    8448
#define OFF_Y    17152
#define OFF_A    25856
#define OFF_STAR 26368
#define OFF_V2A  26496
#define OFF_V2B  26624
#define OFF_MS   26752
#define OFF_BR   26816
#define OFF_PA   26880
#define OFF_PB   27008
#define SM_FLOATS 27136
#define SM_BYTES (SM_FLOATS*4 + 64*68)

#define TS    272
#define THALF 17408
#define ATT_S 144
#define ATT_HALF 9216
#define GWS   144
#define GWHALF (128*144)

__device__ float g_M1T[16384];   // (q1 @ k1^T)^T — coalesced column access
__device__ float g_M2T[16384];   // (k2 @ q2^T)^T

__device__ __forceinline__ uint32_t smem_u32(const void* p) {
    uint32_t a;
    asm("{ .reg .u64 t; cvta.to.shared.u64 t, %1; cvt.u32.u64 %0, t; }" : "=r"(a) : "l"(p));
    return a;
}
__device__ __forceinline__ uint32_t pack_bf2(__nv_bfloat16 a, __nv_bfloat16 b) {
    __nv_bfloat162 v = __halves2bfloat162(a, b);
    return *reinterpret_cast<uint32_t*>(&v);
}
__device__ __forceinline__ void cvt_hilo(float2 v, uint32_t& hi, uint32_t& lo) {
    __nv_bfloat16 h0 = __float2bfloat16_rn(v.x), h1 = __float2bfloat16_rn(v.y);
    hi = pack_bf2(h0, h1);
    lo = pack_bf2(__float2bfloat16_rn(v.x - __bfloat162float(h0)),
                  __float2bfloat16_rn(v.y - __bfloat162float(h1)));
}

#define LDSM4(r, addr) \
    asm volatile("ldmatrix.sync.aligned.m8n8.x4.shared.b16 {%0,%1,%2,%3}, [%4];" \
        : "=r"((r)[0]), "=r"((r)[1]), "=r"((r)[2]), "=r"((r)[3]) : "r"(addr))
#define LDSM4T(r, addr) \
    asm volatile("ldmatrix.sync.aligned.m8n8.x4.trans.shared.b16 {%0,%1,%2,%3}, [%4];" \
        : "=r"((r)[0]), "=r"((r)[1]), "=r"((r)[2]), "=r"((r)[3]) : "r"(addr))
#define MMA16816(c0,c1,c2,c3, a, b0,b1) \
    asm volatile("mma.sync.aligned.m16n8k16.row.col.f32.bf16.bf16.f32 " \
        "{%0,%1,%2,%3}, {%4,%5,%6,%7}, {%8,%9}, {%0,%1,%2,%3};" \
        : "+f"(c0), "+f"(c1), "+f"(c2), "+f"(c3) \
        : "r"((a)[0]), "r"((a)[1]), "r"((a)[2]), "r"((a)[3]), "r"(b0), "r"(b1))

__device__ __forceinline__ void build_tile(const float* S, const float* vec,
                                           char* tile, int tid) {
    for (int p = tid; p < 4096; p += 256) {
        int row = p >> 6, d = (p & 63) << 1;
        float2 sv = *reinterpret_cast<const float2*>(&S[row * NPAD + d]);
        float x0 = sv.x, x1 = sv.y;
        if (vec) { x0 *= vec[d]; x1 *= vec[d + 1]; }
        uint32_t hi, lo;
        cvt_hilo(make_float2(x0, x1), hi, lo);
        int off = row * TS + d * 2;
        *reinterpret_cast<uint32_t*>(tile + off)         = hi;
        *reinterpret_cast<uint32_t*>(tile + THALF + off) = lo;
    }
}

__global__ void prep_kernel(const float* __restrict__ q1, const float* __restrict__ k1,
                            const float* __restrict__ q2, const float* __restrict__ k2) {
    int o = blockIdx.x * 256 + threadIdx.x;
    int m = o >> 14, idx = o & 16383;
    int t = idx >> 7, c = idx & 127;
    const float* X = m ? k2 : q1;
    const float* Y = m ? q2 : k1;
    float acc = 0.f;
    const float4* xr = reinterpret_cast<const float4*>(X + t * 128);
    const float4* yr = reinterpret_cast<const float4*>(Y + c * 128);
    #pragma unroll 8
    for (int d = 0; d < 32; d++) {
        float4 xv = xr[d], yv = yr[d];
        acc += xv.x * yv.x + xv.y * yv.y + xv.z * yv.z + xv.w * yv.w;
    }
    (m ? g_M2T : g_M1T)[c * 128 + t] = acc;
}

__global__ void __launch_bounds__(256, 2)
star_agg_kernel(const float* __restrict__ hidden, const int* __restrict__ adj,
                const float* __restrict__ mask,
                const float* __restrict__ a0, const float* __restrict__ a1,
                const float* __restrict__ a2, const float* __restrict__ a3,
                const float* __restrict__ wlin,
                float* __restrict__ outp, float* __restrict__ starp)
{
    extern __shared__ float sm[];
    float* S    = sm + OFF_S;
    float* A    = sm + OFF_A;
    float* STAR = sm + OFF_STAR;
    float* V2A  = sm + OFF_V2A;
    float* V2B  = sm + OFF_V2B;
    float* MS   = sm + OFF_MS;
    float* BR   = sm + OFF_BR;
    float* PA   = sm + OFF_PA;
    float* PB   = sm + OFF_PB;
    char*  XT   = (char*)(sm + OFF_X);
    char*  YT   = (char*)(sm + OFF_Y);
    unsigned char* ADJ = (unsigned char*)(sm + SM_FLOATS);  // [i][j] stride 68

    const int tid = threadIdx.x, lane = tid & 31, warp = tid >> 5, b = blockIdx.x;
    const uint32_t smb = smem_u32(sm);
    const uint32_t XH = smb + OFF_X * 4;
    const uint32_t YH = smb + OFF_Y * 4;
    const float* hg = hidden + (size_t)b * (NN * 128);
    const int*   ag = adj + (size_t)b * (NN * NN);

    for (int idx = tid; idx < NN * 32; idx += 256) {
        int i = idx >> 5, c4 = (idx & 31) << 2;
        *reinterpret_cast<float4*>(&S[i * NPAD + c4]) = reinterpret_cast<const float4*>(hg)[idx];
    }
    for (int idx = tid; idx < NN * NN; idx += 256)
        ADJ[(idx >> 6) * 68 + (idx & 63)] = (unsigned char)ag[idx];
    if (tid < 128) {
        A[tid] = a0[tid]; A[128 + tid] = a1[tid];
        A[256 + tid] = a2[tid]; A[384 + tid] = a3[tid];
    }
    if (tid < 64) MS[tid] = mask[b * NN + tid];
    __syncthreads();
    build_tile(S, nullptr, XT, tid);   // persistent X tile
    if (tid < 128) {
        float acc = 0.f, msum = 0.f;
        #pragma unroll 8
        for (int i = 0; i < NN; i++) { acc += S[i * NPAD + tid] * MS[i]; msum += MS[i]; }
        STAR[tid] = acc / msum;
    }
    __syncthreads();

    const float RSQ = 0.088388347648318447f;
    const int mstrip = warp & 3, nhalf = warp >> 2;
    const int R0 = mstrip * 16, N0 = nhalf * 32;
    const int g = lane >> 2, i0 = R0 + g;
    const int m4 = lane >> 3;
    const uint32_t abase = XH + (uint32_t)(R0 + (lane & 7) + ((m4 & 1) << 3)) * TS
                         + ((m4 >> 1) << 4);
    // x4 B-operand base: lanes 0-15 -> nt_lo, 16-31 -> nt_hi ; bit3 -> k-half byte offset
    const int rsel4 = ((lane >> 4) & 1) * 8 + (lane & 7);
    const int csel4 = ((lane >> 3) & 1) * 16;
    const uint32_t bbase4 = YH + (uint32_t)(N0 + rsel4) * TS + csel4;

    // preload adj codes (same for both steps)
    unsigned short adjp[8];
    #pragma unroll
    for (int nt = 0; nt < 4; nt++) {
        int j0 = N0 + nt * 8 + ((lane & 3) << 1);
        adjp[nt * 2]     = *reinterpret_cast<const unsigned short*>(&ADJ[i0 * 68 + j0]);
        adjp[nt * 2 + 1] = *reinterpret_cast<const unsigned short*>(&ADJ[(i0 + 8) * 68 + j0]);
    }

    for (int step = 0; step < 2; step++) {
        // ===== star matvecs (coalesced, parallel pairs) =====
        {
            const int gg = warp >> 2;
            const int t = tid & 127;
            const float* MT = gg ? g_M2T : g_M1T;
            float* V2g = gg ? V2B : V2A;
            float s0 = 0.f, s1 = 0.f, s2 = 0.f, s3 = 0.f;
            #pragma unroll 8
            for (int c = 0; c < 128; c += 4) {
                s0 += STAR[c]     * MT[c * 128 + t];
                s1 += STAR[c + 1] * MT[(c + 1) * 128 + t];
                s2 += STAR[c + 2] * MT[(c + 2) * 128 + t];
                s3 += STAR[c + 3] * MT[(c + 3) * 128 + t];
            }
            V2g[t] = (s0 + s1) + (s2 + s3);
        }

        // ===== A frags (X tile, current S) =====
        uint32_t ah[32], al[32];
        #pragma unroll
        for (int kt = 0; kt < 8; kt++) {
            LDSM4(&ah[kt * 4], abase + kt * 32);
            LDSM4(&al[kt * 4], abase + THALF + kt * 32);
        }

        // ===== e-logits: per k build Y, MMA (x4 B-loads), reg-select =====
        float sel[4][4];
        #pragma unroll
        for (int nt = 0; nt < 4; nt++)
            #pragma unroll
            for (int q = 0; q < 4; q++) sel[nt][q] = NEG_BIG;
        for (int k = 0; k < 4; k++) {
            if (k > 0) __syncthreads();            // prev MMA reads done (k=0 covered by prior sync)
            build_tile(S, A + k * 128, YT, tid);
            __syncthreads();
            const unsigned short code2 = (unsigned short)(k + 1);
            #pragma unroll
            for (int ntp = 0; ntp < 2; ntp++) {
                float c0 = 0.f, c1 = 0.f, c2 = 0.f, c3 = 0.f;   // nt = 2ntp
                float d0 = 0.f, d1 = 0.f, d2 = 0.f, d3 = 0.f;   // nt = 2ntp+1
                #pragma unroll
                for (int kt = 0; kt < 8; kt++) {
                    uint32_t bq[4], bql[4];
                    uint32_t ba = bbase4 + ntp * (16 * TS) + kt * 32;
                    LDSM4(bq, ba);
                    LDSM4(bql, ba + THALF);
                    MMA16816(c0, c1, c2, c3, &ah[kt * 4], bq[0], bq[1]);
                    MMA16816(c0, c1, c2, c3, &ah[kt * 4], bql[0], bql[1]);
                    MMA16816(c0, c1, c2, c3, &al[kt * 4], bq[0], bq[1]);
                    MMA16816(d0, d1, d2, d3, &ah[kt * 4], bq[2], bq[3]);
                    MMA16816(d0, d1, d2, d3, &ah[kt * 4], bql[2], bql[3]);
                    MMA16816(d0, d1, d2, d3, &al[kt * 4], bq[2], bq[3]);
                }
                int nt0 = 2 * ntp, nt1 = 2 * ntp + 1;
                unsigned short p0 = adjp[nt0 * 2], p1 = adjp[nt0 * 2 + 1];
                if ((p0 & 0xFF) == code2)  sel[nt0][0] = (c0 >= 0.f) ? c0 : 0.2f * c0;
                if ((p0 >> 8)   == code2)  sel[nt0][1] = (c1 >= 0.f) ? c1 : 0.2f * c1;
                if ((p1 & 0xFF) == code2)  sel[nt0][2] = (c2 >= 0.f) ? c2 : 0.2f * c2;
                if ((p1 >> 8)   == code2)  sel[nt0][3] = (c3 >= 0.f) ? c3 : 0.2f * c3;
                p0 = adjp[nt1 * 2]; p1 = adjp[nt1 * 2 + 1];
                if ((p0 & 0xFF) == code2)  sel[nt1][0] = (d0 >= 0.f) ? d0 : 0.2f * d0;
                if ((p0 >> 8)   == code2)  sel[nt1][1] = (d1 >= 0.f) ? d1 : 0.2f * d1;
                if ((p1 & 0xFF) == code2)  sel[nt1][2] = (d2 >= 0.f) ? d2 : 0.2f * d2;
                if ((p1 >> 8)   == code2)  sel[nt1][3] = (d3 >= 0.f) ? d3 : 0.2f * d3;
            }
        }

        // ===== fragment softmax =====
        float m0 = NEG_BIG, m1 = NEG_BIG;
        #pragma unroll
        for (int nt = 0; nt < 4; nt++) {
            m0 = fmaxf(m0, fmaxf(sel[nt][0], sel[nt][1]));
            m1 = fmaxf(m1, fmaxf(sel[nt][2], sel[nt][3]));
        }
        m0 = fmaxf(m0, __shfl_xor_sync(0xffffffffu, m0, 1));
        m0 = fmaxf(m0, __shfl_xor_sync(0xffffffffu, m0, 2));
        m1 = fmaxf(m1, __shfl_xor_sync(0xffffffffu, m1, 1));
        m1 = fmaxf(m1, __shfl_xor_sync(0xffffffffu, m1, 2));
        if ((lane & 3) == 0) { PA[i0 * 2 + nhalf] = m0; PA[(i0 + 8) * 2 + nhalf] = m1; }
        __syncthreads();
        m0 = fmaxf(PA[i0 * 2], PA[i0 * 2 + 1]);
        m1 = fmaxf(PA[(i0 + 8) * 2], PA[(i0 + 8) * 2 + 1]);
        float s0 = 0.f, s1 = 0.f;
        #pragma unroll
        for (int nt = 0; nt < 4; nt++) {
            sel[nt][0] = __expf(sel[nt][0] - m0); s0 += sel[nt][0];
            sel[nt][1] = __expf(sel[nt][1] - m0); s0 += sel[nt][1];
            sel[nt][2] = __expf(sel[nt][2] - m1); s1 += sel[nt][2];
            sel[nt][3] = __expf(sel[nt][3] - m1); s1 += sel[nt][3];
        }
        s0 += __shfl_xor_sync(0xffffffffu, s0, 1);
        s0 += __shfl_xor_sync(0xffffffffu, s0, 2);
        s1 += __shfl_xor_sync(0xffffffffu, s1, 1);
        s1 += __shfl_xor_sync(0xffffffffu, s1, 2);
        if ((lane & 3) == 0) { PB[i0 * 2 + nhalf] = s0; PB[(i0 + 8) * 2 + nhalf] = s1; }
        __syncthreads();
        float inv0 = 1.f / (PB[i0 * 2] + PB[i0 * 2 + 1]);
        float inv1 = 1.f / (PB[(i0 + 8) * 2] + PB[(i0 + 8) * 2 + 1]);

        // ===== write ATT tile =====
        #pragma unroll
        for (int nt = 0; nt < 4; nt++) {
            int j0 = N0 + nt * 8 + ((lane & 3) << 1);
            uint32_t hi, lo;
            cvt_hilo(make_float2(sel[nt][0] * inv0, sel[nt][1] * inv0), hi, lo);
            int off = i0 * ATT_S + j0 * 2;
            *reinterpret_cast<uint32_t*>(YT + off)            = hi;
            *reinterpret_cast<uint32_t*>(YT + ATT_HALF + off) = lo;
            cvt_hilo(make_float2(sel[nt][2] * inv1, sel[nt][3] * inv1), hi, lo);
            off = (i0 + 8) * ATT_S + j0 * 2;
            *reinterpret_cast<uint32_t*>(YT + off)            = hi;
            *reinterpret_cast<uint32_t*>(YT + ATT_HALF + off) = lo;
        }
        __syncthreads();

        // ===== T = att @ S (A from ATT, B = X^T, x4.trans loads) =====
        {
            uint32_t aah[16], aal[16];
            uint32_t tabase = YH + (uint32_t)(R0 + (lane & 7) + ((m4 & 1) << 3)) * ATT_S
                            + ((m4 >> 1) << 4);
            #pragma unroll
            for (int kt = 0; kt < 4; kt++) {
                LDSM4(&aah[kt * 4], tabase + kt * 32);
                LDSM4(&aal[kt * 4], tabase + ATT_HALF + kt * 32);
            }
            const int N0d = nhalf * 64;
            // x4.trans base: lanes 0-15 address k-rows, lanes 16-31 address nt+1 column window
            const uint32_t t4base = XH + (uint32_t)(lane & 15) * TS
                                  + (uint32_t)N0d * 2 + ((lane >> 4) & 1) * 16;
            float tc[8][4];
            #pragma unroll
            for (int nt = 0; nt < 8; nt++)
                #pragma unroll
                for (int q = 0; q < 4; q++) tc[nt][q] = 0.f;
            #pragma unroll
            for (int ntp = 0; ntp < 4; ntp++) {
                #pragma unroll
                for (int kt = 0; kt < 4; kt++) {
                    uint32_t bq[4], bql[4];
                    uint32_t ba = t4base + (uint32_t)(kt * 16) * TS + ntp * 32;
                    LDSM4T(bq, ba);
                    LDSM4T(bql, ba + THALF);
                    int n0 = 2 * ntp, n1 = 2 * ntp + 1;
                    MMA16816(tc[n0][0], tc[n0][1], tc[n0][2], tc[n0][3], &aah[kt * 4], bq[0], bq[1]);
                    MMA16816(tc[n0][0], tc[n0][1], tc[n0][2], tc[n0][3], &aah[kt * 4], bql[0], bql[1]);
                    MMA16816(tc[n0][0], tc[n0][1], tc[n0][2], tc[n0][3], &aal[kt * 4], bq[0], bq[1]);
                    MMA16816(tc[n1][0], tc[n1][1], tc[n1][2], tc[n1][3], &aah[kt * 4], bq[2], bq[3]);
                    MMA16816(tc[n1][0], tc[n1][1], tc[n1][2], tc[n1][3], &aah[kt * 4], bql[2], bql[3]);
                    MMA16816(tc[n1][0], tc[n1][1], tc[n1][2], tc[n1][3], &aal[kt * 4], bq[2], bq[3]);
                }
            }

            float pa0 = 0.f, pa1 = 0.f;
            #pragma unroll
            for (int nt = 0; nt < 8; nt++) {
                int d0 = N0d + nt * 8 + ((lane & 3) << 1);
                float2 va = *reinterpret_cast<const float2*>(&V2A[d0]);
                pa0 += tc[nt][0] * va.x + tc[nt][1] * va.y;
                pa1 += tc[nt][2] * va.x + tc[nt][3] * va.y;
            }
            pa0 += __shfl_xor_sync(0xffffffffu, pa0, 1);
            pa0 += __shfl_xor_sync(0xffffffffu, pa0, 2);
            pa1 += __shfl_xor_sync(0xffffffffu, pa1, 1);
            pa1 += __shfl_xor_sync(0xffffffffu, pa1, 2);
            if ((lane & 3) == 0) { PA[i0 * 2 + nhalf] = pa0; PA[(i0 + 8) * 2 + nhalf] = pa1; }
            __syncthreads();
            float al0 = (PA[i0 * 2] + PA[i0 * 2 + 1]) * RSQ;
            float al1 = (PA[(i0 + 8) * 2] + PA[(i0 + 8) * 2 + 1]) * RSQ;

            float pb0 = 0.f, pb1 = 0.f;
            #pragma unroll
            for (int nt = 0; nt < 8; nt++) {
                int d0 = N0d + nt * 8 + ((lane & 3) << 1);
                float2 st = *reinterpret_cast<const float2*>(&STAR[d0]);
                float2 vb = *reinterpret_cast<const float2*>(&V2B[d0]);
                float n0x = (1.f - al0) * tc[nt][0] + al0 * st.x;
                float n0y = (1.f - al0) * tc[nt][1] + al0 * st.y;
                float n1x = (1.f - al1) * tc[nt][2] + al1 * st.x;
                float n1y = (1.f - al1) * tc[nt][3] + al1 * st.y;
                *reinterpret_cast<float2*>(&S[i0 * NPAD + d0])       = make_float2(n0x, n0y);
                *reinterpret_cast<float2*>(&S[(i0 + 8) * NPAD + d0]) = make_float2(n1x, n1y);
                uint32_t hi, lo;
                int off = i0 * TS + d0 * 2;
                cvt_hilo(make_float2(n0x, n0y), hi, lo);
                *reinterpret_cast<uint32_t*>(XT + off)         = hi;
                *reinterpret_cast<uint32_t*>(XT + THALF + off) = lo;
                off = (i0 + 8) * TS + d0 * 2;
                cvt_hilo(make_float2(n1x, n1y), hi, lo);
                *reinterpret_cast<uint32_t*>(XT + off)         = hi;
                *reinterpret_cast<uint32_t*>(XT + THALF + off) = lo;
                pb0 += n0x * vb.x + n0y * vb.y;
                pb1 += n1x * vb.x + n1y * vb.y;
            }
            pb0 += __shfl_xor_sync(0xffffffffu, pb0, 1);
            pb0 += __shfl_xor_sync(0xffffffffu, pb0, 2);
            pb1 += __shfl_xor_sync(0xffffffffu, pb1, 1);
            pb1 += __shfl_xor_sync(0xffffffffu, pb1, 2);
            if ((lane & 3) == 0) { PB[i0 * 2 + nhalf] = pb0; PB[(i0 + 8) * 2 + nhalf] = pb1; }
        }
        __syncthreads();

        if (warp == 0) {
            float b0 = (MS[lane] == 0.f)      ? __int_as_float(0xff800000)
                                              : (PB[lane * 2] + PB[lane * 2 + 1]) * RSQ;
            float b1 = (MS[lane + 32] == 0.f) ? __int_as_float(0xff800000)
                                              : (PB[(lane + 32) * 2] + PB[(lane + 32) * 2 + 1]) * RSQ;
            float m = fmaxf(b0, b1);
            #pragma unroll
            for (int o = 16; o > 0; o >>= 1) m = fmaxf(m, __shfl_xor_sync(0xffffffffu, m, o));
            float e0 = __expf(b0 - m), e1 = __expf(b1 - m);
            float sE = e0 + e1;
            #pragma unroll
            for (int o = 16; o > 0; o >>= 1) sE += __shfl_xor_sync(0xffffffffu, sE, o);
            float inv = 1.f / sE;
            BR[lane] = e0 * inv; BR[lane + 32] = e1 * inv;
        }
        __syncthreads();
        if (tid < 128) {
            float acc = 0.f;
            #pragma unroll 8
            for (int j = 0; j < 64; j++) acc += BR[j] * S[j * NPAD + tid];
            STAR[tid] = acc;
        }
        __syncthreads();
    }

    // ===== gate: C = cat(hidden,S) @ W^T  (x4 B-loads) =====
    {
        char* WT = YT;
        const uint32_t WTH = YH;
        const int N0g = nhalf * 64;
        const uint32_t gbase4 = WTH + (uint32_t)(N0g + rsel4) * GWS + csel4;
        float acc[8][4];
        #pragma unroll
        for (int nt = 0; nt < 8; nt++)
            #pragma unroll
            for (int q = 0; q < 4; q++) acc[nt][q] = 0.f;

        for (int chunk = 0; chunk < 4; chunk++) {
            const int c0 = chunk * 64;
            __syncthreads();
            for (int idx = tid; idx < 2048; idx += 256) {
                int o = idx >> 4, p4 = idx & 15;
                float4 w = __ldg(reinterpret_cast<const float4*>(&wlin[o * 256 + c0 + p4 * 4]));
                uint32_t h0, l0, h1, l1;
                cvt_hilo(make_float2(w.x, w.y), h0, l0);
                cvt_hilo(make_float2(w.z, w.w), h1, l1);
                *reinterpret_cast<uint2*>(WT + o * GWS + p4 * 8)          = make_uint2(h0, h1);
                *reinterpret_cast<uint2*>(WT + GWHALF + o * GWS + p4 * 8) = make_uint2(l0, l1);
            }
            __syncthreads();
            const bool fh2 = chunk < 2;
            const int cb = fh2 ? c0 : (c0 - 128);
            const int r0 = i0;
            #pragma unroll
            for (int kt = 0; kt < 4; kt++) {
                uint32_t fah[4], fal[4];
                if (fh2) {
                    int cc = cb + kt * 16 + ((lane & 3) << 1);
                    float2 x00 = __ldg(reinterpret_cast<const float2*>(&hg[r0 * 128 + cc]));
                    float2 x10 = __ldg(reinterpret_cast<const float2*>(&hg[(r0 + 8) * 128 + cc]));
                    float2 x01 = __ldg(reinterpret_cast<const float2*>(&hg[r0 * 128 + cc + 8]));
                    float2 x11 = __ldg(reinterpret_cast<const float2*>(&hg[(r0 + 8) * 128 + cc + 8]));
                    cvt_hilo(x00, fah[0], fal[0]);
                    cvt_hilo(x10, fah[1], fal[1]);
                    cvt_hilo(x01, fah[2], fal[2]);
                    cvt_hilo(x11, fah[3], fal[3]);
                } else {
                    uint32_t ab2 = abase + (uint32_t)(cb + kt * 16) * 2;
                    LDSM4(fah, ab2);
                    LDSM4(fal, ab2 + THALF);
                }
                #pragma unroll
                for (int ntp = 0; ntp < 4; ntp++) {
                    uint32_t bq[4], bql[4];
                    uint32_t ba = gbase4 + ntp * (16 * GWS) + kt * 32;
                    LDSM4(bq, ba);
                    LDSM4(bql, ba + GWHALF);
                    int n0 = 2 * ntp, n1 = 2 * ntp + 1;
                    MMA16816(acc[n0][0], acc[n0][1], acc[n0][2], acc[n0][3], fah, bq[0], bq[1]);
                    MMA16816(acc[n0][0], acc[n0][1], acc[n0][2], acc[n0][3], fah, bql[0], bql[1]);
                    MMA16816(acc[n0][0], acc[n0][1], acc[n0][2], acc[n0][3], fal, bq[0], bq[1]);
                    MMA16816(acc[n1][0], acc[n1][1], acc[n1][2], acc[n1][3], fah, bq[2], bq[3]);
                    MMA16816(acc[n1][0], acc[n1][1], acc[n1][2], acc[n1][3], fah, bql[2], bql[3]);
                    MMA16816(acc[n1][0], acc[n1][1], acc[n1][2], acc[n1][3], fal, bq[2], bq[3]);
                }
            }
        }

        float* ob = outp + (size_t)b * (NN * 128);
        const int r0 = i0;
        #pragma unroll
        for (int nt = 0; nt < 8; nt++) {
            int o0 = N0g + nt * 8 + ((lane & 3) << 1);
            float2 h0 = __ldg(reinterpret_cast<const float2*>(&hg[r0 * 128 + o0]));
            float2 s0v = *reinterpret_cast<const float2*>(&S[r0 * NPAD + o0]);
            float2 h1 = __ldg(reinterpret_cast<const float2*>(&hg[(r0 + 8) * 128 + o0]));
            float2 s1v = *reinterpret_cast<const float2*>(&S[(r0 + 8) * NPAD + o0]);
            float g00 = 1.f / (1.f + __expf(-acc[nt][0]));
            float g01 = 1.f / (1.f + __expf(-acc[nt][1]));
            float g10 = 1.f / (1.f + __expf(-acc[nt][2]));
            float g11 = 1.f / (1.f + __expf(-acc[nt][3]));
            float2 r0v, r1v;
            r0v.x = g00 * h0.x + (1.f - g00) * s0v.x;
            r0v.y = g01 * h0.y + (1.f - g01) * s0v.y;
            r1v.x = g10 * h1.x + (1.f - g10) * s1v.x;
            r1v.y = g11 * h1.y + (1.f - g11) * s1v.y;
            *reinterpret_cast<float2*>(&ob[r0 * 128 + o0])       = r0v;
            *reinterpret_cast<float2*>(&ob[(r0 + 8) * 128 + o0]) = r1v;
        }
    }
    if (tid < 128) starp[(size_t)b * 128 + tid] = STAR[tid];
}

extern "C" void kernel_launch(void* const* d_in, const int* in_sizes, int n_in,
                              void* d_out, int out_size) {
    float* outp  = (float*)d_out;
    float* starp = outp + (size_t)NB * NN * 128;

    prep_kernel<<<128, 256>>>((const float*)d_in[7], (const float*)d_in[8],
                              (const float*)d_in[9], (const float*)d_in[10]);
    cudaFuncSetAttribute(star_agg_kernel, cudaFuncAttributeMaxDynamicSharedMemorySize, SM_BYTES);
    star_agg_kernel<<<NB, 256, SM_BYTES>>>(
        (const float*)d_in[0], (const int*)d_in[1], (const float*)d_in[2],
        (const float*)d_in[3], (const float*)d_in[4], (const float*)d_in[5], (const float*)d_in[6],
        (const float*)d_in[11], outp, starp);
}

// round 15
// speedup vs baseline: 1.2895x; 1.0069x over previous
#include <cuda_runtime.h>
#include <cuda_bf16.h>
#include <cstdint>

#define NB   2048
#define NN   64
#define NPAD 132
#define NEG_BIG (-9000000000000000.0f)

#define OFF_S    0
#define OFF_X    8448
#define OFF_Y    17152
#define OFF_A    25856
#define OFF_STAR 26368
#define OFF_V2A  26496
#define OFF_V2B  26624
#define OFF_MS   26752
#define OFF_BR   26816
#define OFF_PA   26880
#define OFF_PB   27008
#define SM_FLOATS 27136
#define SM_BYTES (SM_FLOATS*4 + 64*68)

#define TS    272
#define THALF 17408
#define ATT_S 144
#define ATT_HALF 9216
#define GWS   144
#define GWHALF (128*144)

__device__ float g_M1T[16384];   // (q1 @ k1^T)^T — coalesced column access
__device__ float g_M2T[16384];   // (k2 @ q2^T)^T

__device__ __forceinline__ uint32_t smem_u32(const void* p) {
    uint32_t a;
    asm("{ .reg .u64 t; cvta.to.shared.u64 t, %1; cvt.u32.u64 %0, t; }" : "=r"(a) : "l"(p));
    return a;
}
__device__ __forceinline__ uint32_t pack_bf2(__nv_bfloat16 a, __nv_bfloat16 b) {
    __nv_bfloat162 v = __halves2bfloat162(a, b);
    return *reinterpret_cast<uint32_t*>(&v);
}
__device__ __forceinline__ void cvt_hilo(float2 v, uint32_t& hi, uint32_t& lo) {
    __nv_bfloat16 h0 = __float2bfloat16_rn(v.x), h1 = __float2bfloat16_rn(v.y);
    hi = pack_bf2(h0, h1);
    lo = pack_bf2(__float2bfloat16_rn(v.x - __bfloat162float(h0)),
                  __float2bfloat16_rn(v.y - __bfloat162float(h1)));
}

#define LDSM4(r, addr) \
    asm volatile("ldmatrix.sync.aligned.m8n8.x4.shared.b16 {%0,%1,%2,%3}, [%4];" \
        : "=r"((r)[0]), "=r"((r)[1]), "=r"((r)[2]), "=r"((r)[3]) : "r"(addr))
#define LDSM4T(r, addr) \
    asm volatile("ldmatrix.sync.aligned.m8n8.x4.trans.shared.b16 {%0,%1,%2,%3}, [%4];" \
        : "=r"((r)[0]), "=r"((r)[1]), "=r"((r)[2]), "=r"((r)[3]) : "r"(addr))
#define MMA16816(c0,c1,c2,c3, a, b0,b1) \
    asm volatile("mma.sync.aligned.m16n8k16.row.col.f32.bf16.bf16.f32 " \
        "{%0,%1,%2,%3}, {%4,%5,%6,%7}, {%8,%9}, {%0,%1,%2,%3};" \
        : "+f"(c0), "+f"(c1), "+f"(c2), "+f"(c3) \
        : "r"((a)[0]), "r"((a)[1]), "r"((a)[2]), "r"((a)[3]), "r"(b0), "r"(b1))

// float4 build: each thread owns column quad d=(tid&31)*4 (loop-invariant -> vec hoisted)
__device__ __forceinline__ void build_tile(const float* S, const float* vec,
                                           char* tile, int tid) {
    const int d = (tid & 31) << 2;
    const int rb = tid >> 5;
    float4 av;
    if (vec) av = *reinterpret_cast<const float4*>(&vec[d]);
    #pragma unroll
    for (int i = 0; i < 8; i++) {
        int row = rb + i * 8;
        float4 sv = *reinterpret_cast<const float4*>(&S[row * NPAD + d]);
        if (vec) { sv.x *= av.x; sv.y *= av.y; sv.z *= av.z; sv.w *= av.w; }
        uint32_t h0, l0, h1, l1;
        cvt_hilo(make_float2(sv.x, sv.y), h0, l0);
        cvt_hilo(make_float2(sv.z, sv.w), h1, l1);
        int off = row * TS + d * 2;
        *reinterpret_cast<uint2*>(tile + off)         = make_uint2(h0, h1);
        *reinterpret_cast<uint2*>(tile + THALF + off) = make_uint2(l0, l1);
    }
}

__global__ void prep_kernel(const float* __restrict__ q1, const float* __restrict__ k1,
                            const float* __restrict__ q2, const float* __restrict__ k2) {
    int o = blockIdx.x * 256 + threadIdx.x;
    int m = o >> 14, idx = o & 16383;
    int t = idx >> 7, c = idx & 127;
    const float* X = m ? k2 : q1;
    const float* Y = m ? q2 : k1;
    float acc = 0.f;
    const float4* xr = reinterpret_cast<const float4*>(X + t * 128);
    const float4* yr = reinterpret_cast<const float4*>(Y + c * 128);
    #pragma unroll 8
    for (int d = 0; d < 32; d++) {
        float4 xv = xr[d], yv = yr[d];
        acc += xv.x * yv.x + xv.y * yv.y + xv.z * yv.z + xv.w * yv.w;
    }
    (m ? g_M2T : g_M1T)[c * 128 + t] = acc;
}

__global__ void __launch_bounds__(256, 2)
star_agg_kernel(const float* __restrict__ hidden, const int* __restrict__ adj,
                const float* __restrict__ mask,
                const float* __restrict__ a0, const float* __restrict__ a1,
                const float* __restrict__ a2, const float* __restrict__ a3,
                const float* __restrict__ wlin,
                float* __restrict__ outp, float* __restrict__ starp)
{
    extern __shared__ float sm[];
    float* S    = sm + OFF_S;
    float* A    = sm + OFF_A;
    float* STAR = sm + OFF_STAR;
    float* V2A  = sm + OFF_V2A;
    float* V2B  = sm + OFF_V2B;
    float* MS   = sm + OFF_MS;
    float* BR   = sm + OFF_BR;
    float* PA   = sm + OFF_PA;
    float* PB   = sm + OFF_PB;
    char*  XT   = (char*)(sm + OFF_X);
    char*  YT   = (char*)(sm + OFF_Y);
    unsigned char* ADJ = (unsigned char*)(sm + SM_FLOATS);  // [i][j] stride 68

    const int tid = threadIdx.x, lane = tid & 31, warp = tid >> 5, b = blockIdx.x;
    const uint32_t smb = smem_u32(sm);
    const uint32_t XH = smb + OFF_X * 4;
    const uint32_t YH = smb + OFF_Y * 4;
    const float* hg = hidden + (size_t)b * (NN * 128);
    const int*   ag = adj + (size_t)b * (NN * NN);

    for (int idx = tid; idx < NN * 32; idx += 256) {
        int i = idx >> 5, c4 = (idx & 31) << 2;
        *reinterpret_cast<float4*>(&S[i * NPAD + c4]) = reinterpret_cast<const float4*>(hg)[idx];
    }
    for (int idx = tid; idx < NN * NN; idx += 256)
        ADJ[(idx >> 6) * 68 + (idx & 63)] = (unsigned char)ag[idx];
    if (tid < 128) {
        A[tid] = a0[tid]; A[128 + tid] = a1[tid];
        A[256 + tid] = a2[tid]; A[384 + tid] = a3[tid];
    }
    if (tid < 64) MS[tid] = mask[b * NN + tid];
    __syncthreads();
    build_tile(S, nullptr, XT, tid);
    if (tid < 128) {
        float acc = 0.f, msum = 0.f;
        #pragma unroll 8
        for (int i = 0; i < NN; i++) { acc += S[i * NPAD + tid] * MS[i]; msum += MS[i]; }
        STAR[tid] = acc / msum;
    }
    __syncthreads();

    const float RSQ = 0.088388347648318447f;
    const int mstrip = warp & 3, nhalf = warp >> 2;
    const int R0 = mstrip * 16, N0 = nhalf * 32;
    const int g = lane >> 2, i0 = R0 + g;
    const int m4 = lane >> 3;
    const uint32_t abase = XH + (uint32_t)(R0 + (lane & 7) + ((m4 & 1) << 3)) * TS
                         + ((m4 >> 1) << 4);
    const int rsel4 = ((lane >> 4) & 1) * 8 + (lane & 7);
    const int csel4 = ((lane >> 3) & 1) * 16;
    const uint32_t bbase4 = YH + (uint32_t)(N0 + rsel4) * TS + csel4;

    unsigned short adjp[8];
    #pragma unroll
    for (int nt = 0; nt < 4; nt++) {
        int j0 = N0 + nt * 8 + ((lane & 3) << 1);
        adjp[nt * 2]     = *reinterpret_cast<const unsigned short*>(&ADJ[i0 * 68 + j0]);
        adjp[nt * 2 + 1] = *reinterpret_cast<const unsigned short*>(&ADJ[(i0 + 8) * 68 + j0]);
    }

    for (int step = 0; step < 2; step++) {
        // ===== star matvecs (coalesced, parallel pairs) =====
        {
            const int gg = warp >> 2;
            const int t = tid & 127;
            const float* MT = gg ? g_M2T : g_M1T;
            float* V2g = gg ? V2B : V2A;
            float s0 = 0.f, s1 = 0.f, s2 = 0.f, s3 = 0.f;
            #pragma unroll 8
            for (int c = 0; c < 128; c += 4) {
                s0 += STAR[c]     * MT[c * 128 + t];
                s1 += STAR[c + 1] * MT[(c + 1) * 128 + t];
                s2 += STAR[c + 2] * MT[(c + 2) * 128 + t];
                s3 += STAR[c + 3] * MT[(c + 3) * 128 + t];
            }
            V2g[t] = (s0 + s1) + (s2 + s3);
        }

        // ===== A frags (X tile, current S) =====
        uint32_t ah[32], al[32];
        #pragma unroll
        for (int kt = 0; kt < 8; kt++) {
            LDSM4(&ah[kt * 4], abase + kt * 32);
            LDSM4(&al[kt * 4], abase + THALF + kt * 32);
        }

        // ===== e-logits =====
        float sel[4][4];
        #pragma unroll
        for (int nt = 0; nt < 4; nt++)
            #pragma unroll
            for (int q = 0; q < 4; q++) sel[nt][q] = NEG_BIG;
        for (int k = 0; k < 4; k++) {
            if (k > 0) __syncthreads();
            build_tile(S, A + k * 128, YT, tid);
            __syncthreads();
            const unsigned short code2 = (unsigned short)(k + 1);
            #pragma unroll
            for (int ntp = 0; ntp < 2; ntp++) {
                float c0 = 0.f, c1 = 0.f, c2 = 0.f, c3 = 0.f;
                float d0 = 0.f, d1 = 0.f, d2 = 0.f, d3 = 0.f;
                #pragma unroll
                for (int kt = 0; kt < 8; kt++) {
                    uint32_t bq[4], bql[4];
                    uint32_t ba = bbase4 + ntp * (16 * TS) + kt * 32;
                    LDSM4(bq, ba);
                    LDSM4(bql, ba + THALF);
                    MMA16816(c0, c1, c2, c3, &ah[kt * 4], bq[0], bq[1]);
                    MMA16816(c0, c1, c2, c3, &ah[kt * 4], bql[0], bql[1]);
                    MMA16816(c0, c1, c2, c3, &al[kt * 4], bq[0], bq[1]);
                    MMA16816(d0, d1, d2, d3, &ah[kt * 4], bq[2], bq[3]);
                    MMA16816(d0, d1, d2, d3, &ah[kt * 4], bql[2], bql[3]);
                    MMA16816(d0, d1, d2, d3, &al[kt * 4], bq[2], bq[3]);
                }
                int nt0 = 2 * ntp, nt1 = 2 * ntp + 1;
                unsigned short p0 = adjp[nt0 * 2], p1 = adjp[nt0 * 2 + 1];
                if ((p0 & 0xFF) == code2)  sel[nt0][0] = (c0 >= 0.f) ? c0 : 0.2f * c0;
                if ((p0 >> 8)   == code2)  sel[nt0][1] = (c1 >= 0.f) ? c1 : 0.2f * c1;
                if ((p1 & 0xFF) == code2)  sel[nt0][2] = (c2 >= 0.f) ? c2 : 0.2f * c2;
                if ((p1 >> 8)   == code2)  sel[nt0][3] = (c3 >= 0.f) ? c3 : 0.2f * c3;
                p0 = adjp[nt1 * 2]; p1 = adjp[nt1 * 2 + 1];
                if ((p0 & 0xFF) == code2)  sel[nt1][0] = (d0 >= 0.f) ? d0 : 0.2f * d0;
                if ((p0 >> 8)   == code2)  sel[nt1][1] = (d1 >= 0.f) ? d1 : 0.2f * d1;
                if ((p1 & 0xFF) == code2)  sel[nt1][2] = (d2 >= 0.f) ? d2 : 0.2f * d2;
                if ((p1 >> 8)   == code2)  sel[nt1][3] = (d3 >= 0.f) ? d3 : 0.2f * d3;
            }
        }

        // ===== online fragment softmax (single exchange) =====
        float m0 = NEG_BIG, m1 = NEG_BIG;
        #pragma unroll
        for (int nt = 0; nt < 4; nt++) {
            m0 = fmaxf(m0, fmaxf(sel[nt][0], sel[nt][1]));
            m1 = fmaxf(m1, fmaxf(sel[nt][2], sel[nt][3]));
        }
        m0 = fmaxf(m0, __shfl_xor_sync(0xffffffffu, m0, 1));
        m0 = fmaxf(m0, __shfl_xor_sync(0xffffffffu, m0, 2));
        m1 = fmaxf(m1, __shfl_xor_sync(0xffffffffu, m1, 1));
        m1 = fmaxf(m1, __shfl_xor_sync(0xffffffffu, m1, 2));
        float s0 = 0.f, s1 = 0.f;
        #pragma unroll
        for (int nt = 0; nt < 4; nt++) {
            sel[nt][0] = __expf(sel[nt][0] - m0); s0 += sel[nt][0];
            sel[nt][1] = __expf(sel[nt][1] - m0); s0 += sel[nt][1];
            sel[nt][2] = __expf(sel[nt][2] - m1); s1 += sel[nt][2];
            sel[nt][3] = __expf(sel[nt][3] - m1); s1 += sel[nt][3];
        }
        s0 += __shfl_xor_sync(0xffffffffu, s0, 1);
        s0 += __shfl_xor_sync(0xffffffffu, s0, 2);
        s1 += __shfl_xor_sync(0xffffffffu, s1, 1);
        s1 += __shfl_xor_sync(0xffffffffu, s1, 2);
        if ((lane & 3) == 0) {
            PA[i0 * 2 + nhalf] = m0;  PB[i0 * 2 + nhalf] = s0;
            PA[(i0 + 8) * 2 + nhalf] = m1;  PB[(i0 + 8) * 2 + nhalf] = s1;
        }
        __syncthreads();
        float mg0 = fmaxf(PA[i0 * 2], PA[i0 * 2 + 1]);
        float mg1 = fmaxf(PA[(i0 + 8) * 2], PA[(i0 + 8) * 2 + 1]);
        float sg0 = PB[i0 * 2] * __expf(PA[i0 * 2] - mg0)
                  + PB[i0 * 2 + 1] * __expf(PA[i0 * 2 + 1] - mg0);
        float sg1 = PB[(i0 + 8) * 2] * __expf(PA[(i0 + 8) * 2] - mg1)
                  + PB[(i0 + 8) * 2 + 1] * __expf(PA[(i0 + 8) * 2 + 1] - mg1);
        float inv0 = __expf(m0 - mg0) / sg0;
        float inv1 = __expf(m1 - mg1) / sg1;

        // ===== write ATT tile =====
        #pragma unroll
        for (int nt = 0; nt < 4; nt++) {
            int j0 = N0 + nt * 8 + ((lane & 3) << 1);
            uint32_t hi, lo;
            cvt_hilo(make_float2(sel[nt][0] * inv0, sel[nt][1] * inv0), hi, lo);
            int off = i0 * ATT_S + j0 * 2;
            *reinterpret_cast<uint32_t*>(YT + off)            = hi;
            *reinterpret_cast<uint32_t*>(YT + ATT_HALF + off) = lo;
            cvt_hilo(make_float2(sel[nt][2] * inv1, sel[nt][3] * inv1), hi, lo);
            off = (i0 + 8) * ATT_S + j0 * 2;
            *reinterpret_cast<uint32_t*>(YT + off)            = hi;
            *reinterpret_cast<uint32_t*>(YT + ATT_HALF + off) = lo;
        }
        __syncthreads();

        // ===== T = att @ S (A from ATT, B = X^T, x4.trans) =====
        {
            uint32_t aah[16], aal[16];
            uint32_t tabase = YH + (uint32_t)(R0 + (lane & 7) + ((m4 & 1) << 3)) * ATT_S
                            + ((m4 >> 1) << 4);
            #pragma unroll
            for (int kt = 0; kt < 4; kt++) {
                LDSM4(&aah[kt * 4], tabase + kt * 32);
                LDSM4(&aal[kt * 4], tabase + ATT_HALF + kt * 32);
            }
            const int N0d = nhalf * 64;
            const uint32_t t4base = XH + (uint32_t)(lane & 15) * TS
                                  + (uint32_t)N0d * 2 + ((lane >> 4) & 1) * 16;
            float tc[8][4];
            #pragma unroll
            for (int nt = 0; nt < 8; nt++)
                #pragma unroll
                for (int q = 0; q < 4; q++) tc[nt][q] = 0.f;
            #pragma unroll
            for (int ntp = 0; ntp < 4; ntp++) {
                #pragma unroll
                for (int kt = 0; kt < 4; kt++) {
                    uint32_t bq[4], bql[4];
                    uint32_t ba = t4base + (uint32_t)(kt * 16) * TS + ntp * 32;
                    LDSM4T(bq, ba);
                    LDSM4T(bql, ba + THALF);
                    int n0 = 2 * ntp, n1 = 2 * ntp + 1;
                    MMA16816(tc[n0][0], tc[n0][1], tc[n0][2], tc[n0][3], &aah[kt * 4], bq[0], bq[1]);
                    MMA16816(tc[n0][0], tc[n0][1], tc[n0][2], tc[n0][3], &aah[kt * 4], bql[0], bql[1]);
                    MMA16816(tc[n0][0], tc[n0][1], tc[n0][2], tc[n0][3], &aal[kt * 4], bq[0], bq[1]);
                    MMA16816(tc[n1][0], tc[n1][1], tc[n1][2], tc[n1][3], &aah[kt * 4], bq[2], bq[3]);
                    MMA16816(tc[n1][0], tc[n1][1], tc[n1][2], tc[n1][3], &aah[kt * 4], bql[2], bql[3]);
                    MMA16816(tc[n1][0], tc[n1][1], tc[n1][2], tc[n1][3], &aal[kt * 4], bq[2], bq[3]);
                }
            }

            float pa0 = 0.f, pa1 = 0.f;
            #pragma unroll
            for (int nt = 0; nt < 8; nt++) {
                int d0 = N0d + nt * 8 + ((lane & 3) << 1);
                float2 va = *reinterpret_cast<const float2*>(&V2A[d0]);
                pa0 += tc[nt][0] * va.x + tc[nt][1] * va.y;
                pa1 += tc[nt][2] * va.x + tc[nt][3] * va.y;
            }
            pa0 += __shfl_xor_sync(0xffffffffu, pa0, 1);
            pa0 += __shfl_xor_sync(0xffffffffu, pa0, 2);
            pa1 += __shfl_xor_sync(0xffffffffu, pa1, 1);
            pa1 += __shfl_xor_sync(0xffffffffu, pa1, 2);
            if ((lane & 3) == 0) { PA[i0 * 2 + nhalf] = pa0; PA[(i0 + 8) * 2 + nhalf] = pa1; }
            __syncthreads();
            float al0 = (PA[i0 * 2] + PA[i0 * 2 + 1]) * RSQ;
            float al1 = (PA[(i0 + 8) * 2] + PA[(i0 + 8) * 2 + 1]) * RSQ;

            float pb0 = 0.f, pb1 = 0.f;
            #pragma unroll
            for (int nt = 0; nt < 8; nt++) {
                int d0 = N0d + nt * 8 + ((lane & 3) << 1);
                float2 st = *reinterpret_cast<const float2*>(&STAR[d0]);
                float2 vb = *reinterpret_cast<const float2*>(&V2B[d0]);
                float n0x = (1.f - al0) * tc[nt][0] + al0 * st.x;
                float n0y = (1.f - al0) * tc[nt][1] + al0 * st.y;
                float n1x = (1.f - al1) * tc[nt][2] + al1 * st.x;
                float n1y = (1.f - al1) * tc[nt][3] + al1 * st.y;
                *reinterpret_cast<float2*>(&S[i0 * NPAD + d0])       = make_float2(n0x, n0y);
                *reinterpret_cast<float2*>(&S[(i0 + 8) * NPAD + d0]) = make_float2(n1x, n1y);
                uint32_t hi, lo;
                int off = i0 * TS + d0 * 2;
                cvt_hilo(make_float2(n0x, n0y), hi, lo);
                *reinterpret_cast<uint32_t*>(XT + off)         = hi;
                *reinterpret_cast<uint32_t*>(XT + THALF + off) = lo;
                off = (i0 + 8) * TS + d0 * 2;
                cvt_hilo(make_float2(n1x, n1y), hi, lo);
                *reinterpret_cast<uint32_t*>(XT + off)         = hi;
                *reinterpret_cast<uint32_t*>(XT + THALF + off) = lo;
                pb0 += n0x * vb.x + n0y * vb.y;
                pb1 += n1x * vb.x + n1y * vb.y;
            }
            pb0 += __shfl_xor_sync(0xffffffffu, pb0, 1);
            pb0 += __shfl_xor_sync(0xffffffffu, pb0, 2);
            pb1 += __shfl_xor_sync(0xffffffffu, pb1, 1);
            pb1 += __shfl_xor_sync(0xffffffffu, pb1, 2);
            if ((lane & 3) == 0) { PB[i0 * 2 + nhalf] = pb0; PB[(i0 + 8) * 2 + nhalf] = pb1; }
        }
        __syncthreads();

        if (warp == 0) {
            float b0 = (MS[lane] == 0.f)      ? __int_as_float(0xff800000)
                                              : (PB[lane * 2] + PB[lane * 2 + 1]) * RSQ;
            float b1 = (MS[lane + 32] == 0.f) ? __int_as_float(0xff800000)
                                              : (PB[(lane + 32) * 2] + PB[(lane + 32) * 2 + 1]) * RSQ;
            float m = fmaxf(b0, b1);
            #pragma unroll
            for (int o = 16; o > 0; o >>= 1) m = fmaxf(m, __shfl_xor_sync(0xffffffffu, m, o));
            float e0 = __expf(b0 - m), e1 = __expf(b1 - m);
            float sE = e0 + e1;
            #pragma unroll
            for (int o = 16; o > 0; o >>= 1) sE += __shfl_xor_sync(0xffffffffu, sE, o);
            float inv = 1.f / sE;
            BR[lane] = e0 * inv; BR[lane + 32] = e1 * inv;
        }
        __syncthreads();
        if (tid < 128) {
            float acc = 0.f;
            #pragma unroll 8
            for (int j = 0; j < 64; j++) acc += BR[j] * S[j * NPAD + tid];
            STAR[tid] = acc;
        }
        __syncthreads();
    }

    // ===== gate =====
    {
        char* WT = YT;
        const uint32_t WTH = YH;
        const int N0g = nhalf * 64;
        const uint32_t gbase4 = WTH + (uint32_t)(N0g + rsel4) * GWS + csel4;
        float acc[8][4];
        #pragma unroll
        for (int nt = 0; nt < 8; nt++)
            #pragma unroll
            for (int q = 0; q < 4; q++) acc[nt][q] = 0.f;

        for (int chunk = 0; chunk < 4; chunk++) {
            const int c0 = chunk * 64;
            __syncthreads();
            for (int idx = tid; idx < 2048; idx += 256) {
                int o = idx >> 4, p4 = idx & 15;
                float4 w = __ldg(reinterpret_cast<const float4*>(&wlin[o * 256 + c0 + p4 * 4]));
                uint32_t h0, l0, h1, l1;
                cvt_hilo(make_float2(w.x, w.y), h0, l0);
                cvt_hilo(make_float2(w.z, w.w), h1, l1);
                *reinterpret_cast<uint2*>(WT + o * GWS + p4 * 8)          = make_uint2(h0, h1);
                *reinterpret_cast<uint2*>(WT + GWHALF + o * GWS + p4 * 8) = make_uint2(l0, l1);
            }
            __syncthreads();
            const bool fh2 = chunk < 2;
            const int cb = fh2 ? c0 : (c0 - 128);
            const int r0 = i0;
            #pragma unroll
            for (int kt = 0; kt < 4; kt++) {
                uint32_t fah[4], fal[4];
                if (fh2) {
                    int cc = cb + kt * 16 + ((lane & 3) << 1);
                    float2 x00 = __ldg(reinterpret_cast<const float2*>(&hg[r0 * 128 + cc]));
                    float2 x10 = __ldg(reinterpret_cast<const float2*>(&hg[(r0 + 8) * 128 + cc]));
                    float2 x01 = __ldg(reinterpret_cast<const float2*>(&hg[r0 * 128 + cc + 8]));
                    float2 x11 = __ldg(reinterpret_cast<const float2*>(&hg[(r0 + 8) * 128 + cc + 8]));
                    cvt_hilo(x00, fah[0], fal[0]);
                    cvt_hilo(x10, fah[1], fal[1]);
                    cvt_hilo(x01, fah[2], fal[2]);
                    cvt_hilo(x11, fah[3], fal[3]);
                } else {
                    uint32_t ab2 = abase + (uint32_t)(cb + kt * 16) * 2;
                    LDSM4(fah, ab2);
                    LDSM4(fal, ab2 + THALF);
                }
                #pragma unroll
                for (int ntp = 0; ntp < 4; ntp++) {
                    uint32_t bq[4], bql[4];
                    uint32_t ba = gbase4 + ntp * (16 * GWS) + kt * 32;
                    LDSM4(bq, ba);
                    LDSM4(bql, ba + GWHALF);
                    int n0 = 2 * ntp, n1 = 2 * ntp + 1;
                    MMA16816(acc[n0][0], acc[n0][1], acc[n0][2], acc[n0][3], fah, bq[0], bq[1]);
                    MMA16816(acc[n0][0], acc[n0][1], acc[n0][2], acc[n0][3], fah, bql[0], bql[1]);
                    MMA16816(acc[n0][0], acc[n0][1], acc[n0][2], acc[n0][3], fal, bq[0], bq[1]);
                    MMA16816(acc[n1][0], acc[n1][1], acc[n1][2], acc[n1][3], fah, bq[2], bq[3]);
                    MMA16816(acc[n1][0], acc[n1][1], acc[n1][2], acc[n1][3], fah, bql[2], bql[3]);
                    MMA16816(acc[n1][0], acc[n1][1], acc[n1][2], acc[n1][3], fal, bq[2], bq[3]);
                }
            }
        }

        float* ob = outp + (size_t)b * (NN * 128);
        const int r0 = i0;
        #pragma unroll
        for (int nt = 0; nt < 8; nt++) {
            int o0 = N0g + nt * 8 + ((lane & 3) << 1);
            float2 h0 = __ldg(reinterpret_cast<const float2*>(&hg[r0 * 128 + o0]));
            float2 s0v = *reinterpret_cast<const float2*>(&S[r0 * NPAD + o0]);
            float2 h1 = __ldg(reinterpret_cast<const float2*>(&hg[(r0 + 8) * 128 + o0]));
            float2 s1v = *reinterpret_cast<const float2*>(&S[(r0 + 8) * NPAD + o0]);
            float g00 = 1.f / (1.f + __expf(-acc[nt][0]));
            float g01 = 1.f / (1.f + __expf(-acc[nt][1]));
            float g10 = 1.f / (1.f + __expf(-acc[nt][2]));
            float g11 = 1.f / (1.f + __expf(-acc[nt][3]));
            float2 r0v, r1v;
            r0v.x = g00 * h0.x + (1.f - g00) * s0v.x;
            r0v.y = g01 * h0.y + (1.f - g01) * s0v.y;
            r1v.x = g10 * h1.x + (1.f - g10) * s1v.x;
            r1v.y = g11 * h1.y + (1.f - g11) * s1v.y;
            *reinterpret_cast<float2*>(&ob[r0 * 128 + o0])       = r0v;
            *reinterpret_cast<float2*>(&ob[(r0 + 8) * 128 + o0]) = r1v;
        }
    }
    if (tid < 128) starp[(size_t)b * 128 + tid] = STAR[tid];
}

extern "C" void kernel_launch(void* const* d_in, const int* in_sizes, int n_in,
                              void* d_out, int out_size) {
    float* outp  = (float*)d_out;
    float* starp = outp + (size_t)NB * NN * 128;

    prep_kernel<<<128, 256>>>((const float*)d_in[7], (const float*)d_in[8],
                              (const float*)d_in[9], (const float*)d_in[10]);
    cudaFuncSetAttribute(star_agg_kernel, cudaFuncAttributeMaxDynamicSharedMemorySize, SM_BYTES);
    star_agg_kernel<<<NB, 256, SM_BYTES>>>(
        (const float*)d_in[0], (const int*)d_in[1], (const float*)d_in[2],
        (const float*)d_in[3], (const float*)d_in[4], (const float*)d_in[5], (const float*)d_in[6],
        (const float*)d_in[11], outp, starp);
}

// round 16
// speedup vs baseline: 1.3513x; 1.0480x over previous
#include <cuda_runtime.h>
#include <cuda_bf16.h>
#include <cstdint>

#define NB   2048
#define NN   64
#define NPAD 132
#define NEG_BIG (-9000000000000000.0f)

#define OFF_S    0
#define OFF_X    8448
#define OFF_Y    17152
#define OFF_A    25856
#define OFF_STAR 26368
#define OFF_V2A  26496
#define OFF_V2B  26624
#define OFF_MS   26752
#define OFF_BR   26816
#define OFF_PA   26880
#define OFF_PB   27008
#define SM_FLOATS 27136
#define SM_BYTES (SM_FLOATS*4 + 64*68)

#define TS    272
#define THALF 17408
#define ATT_S 144
#define ATT_HALF 9216
#define GWS   144
#define GWHALF (128*144)

__device__ float g_M1T[16384];   // (q1 @ k1^T)^T — coalesced column access
__device__ float g_M2T[16384];   // (k2 @ q2^T)^T

__device__ __forceinline__ uint32_t smem_u32(const void* p) {
    uint32_t a;
    asm("{ .reg .u64 t; cvta.to.shared.u64 t, %1; cvt.u32.u64 %0, t; }" : "=r"(a) : "l"(p));
    return a;
}
__device__ __forceinline__ uint32_t pack_bf2(__nv_bfloat16 a, __nv_bfloat16 b) {
    __nv_bfloat162 v = __halves2bfloat162(a, b);
    return *reinterpret_cast<uint32_t*>(&v);
}
__device__ __forceinline__ void cvt_hilo(float2 v, uint32_t& hi, uint32_t& lo) {
    __nv_bfloat16 h0 = __float2bfloat16_rn(v.x), h1 = __float2bfloat16_rn(v.y);
    hi = pack_bf2(h0, h1);
    lo = pack_bf2(__float2bfloat16_rn(v.x - __bfloat162float(h0)),
                  __float2bfloat16_rn(v.y - __bfloat162float(h1)));
}

#define LDSM4(r, addr) \
    asm volatile("ldmatrix.sync.aligned.m8n8.x4.shared.b16 {%0,%1,%2,%3}, [%4];" \
        : "=r"((r)[0]), "=r"((r)[1]), "=r"((r)[2]), "=r"((r)[3]) : "r"(addr))
#define LDSM4T(r, addr) \
    asm volatile("ldmatrix.sync.aligned.m8n8.x4.trans.shared.b16 {%0,%1,%2,%3}, [%4];" \
        : "=r"((r)[0]), "=r"((r)[1]), "=r"((r)[2]), "=r"((r)[3]) : "r"(addr))
#define MMA16816(c0,c1,c2,c3, a, b0,b1) \
    asm volatile("mma.sync.aligned.m16n8k16.row.col.f32.bf16.bf16.f32 " \
        "{%0,%1,%2,%3}, {%4,%5,%6,%7}, {%8,%9}, {%0,%1,%2,%3};" \
        : "+f"(c0), "+f"(c1), "+f"(c2), "+f"(c3) \
        : "r"((a)[0]), "r"((a)[1]), "r"((a)[2]), "r"((a)[3]), "r"(b0), "r"(b1))
#define BARH(h) asm volatile("bar.sync %0, 128;" :: "r"(1 + (h)) : "memory")

// full-tile build (init only): thread owns col quad d=(tid&31)*4
__device__ __forceinline__ void build_tile(const float* S, char* tile, int tid) {
    const int d = (tid & 31) << 2;
    const int rb = tid >> 5;
    #pragma unroll
    for (int i = 0; i < 8; i++) {
        int row = rb + i * 8;
        float4 sv = *reinterpret_cast<const float4*>(&S[row * NPAD + d]);
        uint32_t h0, l0, h1, l1;
        cvt_hilo(make_float2(sv.x, sv.y), h0, l0);
        cvt_hilo(make_float2(sv.z, sv.w), h1, l1);
        int off = row * TS + d * 2;
        *reinterpret_cast<uint2*>(tile + off)         = make_uint2(h0, h1);
        *reinterpret_cast<uint2*>(tile + THALF + off) = make_uint2(l0, l1);
    }
}

// half-tile build: half hh builds rows [hh*32, hh*32+32), t128 = tid&127
__device__ __forceinline__ void build_tile_half(const float* S, const float* vec,
                                                char* tile, int t128, int hh) {
    const int d = (t128 & 31) << 2;
    const int rb = hh * 32 + (t128 >> 5);
    float4 av = *reinterpret_cast<const float4*>(&vec[d]);
    #pragma unroll
    for (int i = 0; i < 8; i++) {
        int row = rb + i * 4;
        float4 sv = *reinterpret_cast<const float4*>(&S[row * NPAD + d]);
        sv.x *= av.x; sv.y *= av.y; sv.z *= av.z; sv.w *= av.w;
        uint32_t h0, l0, h1, l1;
        cvt_hilo(make_float2(sv.x, sv.y), h0, l0);
        cvt_hilo(make_float2(sv.z, sv.w), h1, l1);
        int off = row * TS + d * 2;
        *reinterpret_cast<uint2*>(tile + off)         = make_uint2(h0, h1);
        *reinterpret_cast<uint2*>(tile + THALF + off) = make_uint2(l0, l1);
    }
}

__global__ void prep_kernel(const float* __restrict__ q1, const float* __restrict__ k1,
                            const float* __restrict__ q2, const float* __restrict__ k2) {
    int o = blockIdx.x * 256 + threadIdx.x;
    int m = o >> 14, idx = o & 16383;
    int t = idx >> 7, c = idx & 127;
    const float* X = m ? k2 : q1;
    const float* Y = m ? q2 : k1;
    float acc = 0.f;
    const float4* xr = reinterpret_cast<const float4*>(X + t * 128);
    const float4* yr = reinterpret_cast<const float4*>(Y + c * 128);
    #pragma unroll 8
    for (int d = 0; d < 32; d++) {
        float4 xv = xr[d], yv = yr[d];
        acc += xv.x * yv.x + xv.y * yv.y + xv.z * yv.z + xv.w * yv.w;
    }
    (m ? g_M2T : g_M1T)[c * 128 + t] = acc;
}

__global__ void __launch_bounds__(256, 2)
star_agg_kernel(const float* __restrict__ hidden, const int* __restrict__ adj,
                const float* __restrict__ mask,
                const float* __restrict__ a0, const float* __restrict__ a1,
                const float* __restrict__ a2, const float* __restrict__ a3,
                const float* __restrict__ wlin,
                float* __restrict__ outp, float* __restrict__ starp)
{
    extern __shared__ float sm[];
    float* S    = sm + OFF_S;
    float* A    = sm + OFF_A;
    float* STAR = sm + OFF_STAR;
    float* V2A  = sm + OFF_V2A;
    float* V2B  = sm + OFF_V2B;
    float* MS   = sm + OFF_MS;
    float* BR   = sm + OFF_BR;
    float* PA   = sm + OFF_PA;
    float* PB   = sm + OFF_PB;
    char*  XT   = (char*)(sm + OFF_X);
    char*  YT   = (char*)(sm + OFF_Y);
    unsigned char* ADJ = (unsigned char*)(sm + SM_FLOATS);  // [i][j] stride 68

    const int tid = threadIdx.x, lane = tid & 31, warp = tid >> 5, b = blockIdx.x;
    const int t128 = tid & 127;
    const uint32_t smb = smem_u32(sm);
    const uint32_t XH = smb + OFF_X * 4;
    const uint32_t YH = smb + OFF_Y * 4;
    const float* hg = hidden + (size_t)b * (NN * 128);
    const int*   ag = adj + (size_t)b * (NN * NN);

    for (int idx = tid; idx < NN * 32; idx += 256) {
        int i = idx >> 5, c4 = (idx & 31) << 2;
        *reinterpret_cast<float4*>(&S[i * NPAD + c4]) = reinterpret_cast<const float4*>(hg)[idx];
    }
    for (int idx = tid; idx < NN * NN; idx += 256)
        ADJ[(idx >> 6) * 68 + (idx & 63)] = (unsigned char)ag[idx];
    if (tid < 128) {
        A[tid] = a0[tid]; A[128 + tid] = a1[tid];
        A[256 + tid] = a2[tid]; A[384 + tid] = a3[tid];
    }
    if (tid < 64) MS[tid] = mask[b * NN + tid];
    __syncthreads();
    build_tile(S, XT, tid);
    if (tid < 128) {
        float acc = 0.f, msum = 0.f;
        #pragma unroll 8
        for (int i = 0; i < NN; i++) { acc += S[i * NPAD + tid] * MS[i]; msum += MS[i]; }
        STAR[tid] = acc / msum;
    }
    __syncthreads();

    const float RSQ = 0.088388347648318447f;
    const int mstrip = warp & 3, nhalf = warp >> 2;   // nhalf == tid>>7
    const int R0 = mstrip * 16, N0 = nhalf * 32;
    const int g = lane >> 2, i0 = R0 + g;
    const int m4 = lane >> 3;
    const uint32_t abase = XH + (uint32_t)(R0 + (lane & 7) + ((m4 & 1) << 3)) * TS
                         + ((m4 >> 1) << 4);
    const int rsel4 = ((lane >> 4) & 1) * 8 + (lane & 7);
    const int csel4 = ((lane >> 3) & 1) * 16;
    const uint32_t bbase4 = YH + (uint32_t)(N0 + rsel4) * TS + csel4;

    unsigned short adjp[8];
    #pragma unroll
    for (int nt = 0; nt < 4; nt++) {
        int j0 = N0 + nt * 8 + ((lane & 3) << 1);
        adjp[nt * 2]     = *reinterpret_cast<const unsigned short*>(&ADJ[i0 * 68 + j0]);
        adjp[nt * 2 + 1] = *reinterpret_cast<const unsigned short*>(&ADJ[(i0 + 8) * 68 + j0]);
    }

    for (int step = 0; step < 2; step++) {
        // ===== star matvecs (coalesced, parallel pairs) =====
        {
            const float* MT = nhalf ? g_M2T : g_M1T;
            float* V2g = nhalf ? V2B : V2A;
            float s0 = 0.f, s1 = 0.f, s2 = 0.f, s3 = 0.f;
            #pragma unroll 8
            for (int c = 0; c < 128; c += 4) {
                s0 += STAR[c]     * MT[c * 128 + t128];
                s1 += STAR[c + 1] * MT[(c + 1) * 128 + t128];
                s2 += STAR[c + 2] * MT[(c + 2) * 128 + t128];
                s3 += STAR[c + 3] * MT[(c + 3) * 128 + t128];
            }
            V2g[t128] = (s0 + s1) + (s2 + s3);
        }

        // ===== A frags (X tile, current S) =====
        uint32_t ah[32], al[32];
        #pragma unroll
        for (int kt = 0; kt < 8; kt++) {
            LDSM4(&ah[kt * 4], abase + kt * 32);
            LDSM4(&al[kt * 4], abase + THALF + kt * 32);
        }

        // ===== e-logits: half-scoped Y build/consume pipeline =====
        float sel[4][4];
        #pragma unroll
        for (int nt = 0; nt < 4; nt++)
            #pragma unroll
            for (int q = 0; q < 4; q++) sel[nt][q] = NEG_BIG;
        for (int k = 0; k < 4; k++) {
            if (k > 0) BARH(nhalf);               // this half's MMA reads of Y rows done
            build_tile_half(S, A + k * 128, YT, t128, nhalf);
            BARH(nhalf);                          // this half's Y rows ready
            const unsigned short code2 = (unsigned short)(k + 1);
            #pragma unroll
            for (int ntp = 0; ntp < 2; ntp++) {
                float c0 = 0.f, c1 = 0.f, c2 = 0.f, c3 = 0.f;
                float d0 = 0.f, d1 = 0.f, d2 = 0.f, d3 = 0.f;
                #pragma unroll
                for (int kt = 0; kt < 8; kt++) {
                    uint32_t bq[4], bql[4];
                    uint32_t ba = bbase4 + ntp * (16 * TS) + kt * 32;
                    LDSM4(bq, ba);
                    LDSM4(bql, ba + THALF);
                    MMA16816(c0, c1, c2, c3, &ah[kt * 4], bq[0], bq[1]);
                    MMA16816(c0, c1, c2, c3, &ah[kt * 4], bql[0], bql[1]);
                    MMA16816(c0, c1, c2, c3, &al[kt * 4], bq[0], bq[1]);
                    MMA16816(d0, d1, d2, d3, &ah[kt * 4], bq[2], bq[3]);
                    MMA16816(d0, d1, d2, d3, &ah[kt * 4], bql[2], bql[3]);
                    MMA16816(d0, d1, d2, d3, &al[kt * 4], bq[2], bq[3]);
                }
                int nt0 = 2 * ntp, nt1 = 2 * ntp + 1;
                unsigned short p0 = adjp[nt0 * 2], p1 = adjp[nt0 * 2 + 1];
                if ((p0 & 0xFF) == code2)  sel[nt0][0] = (c0 >= 0.f) ? c0 : 0.2f * c0;
                if ((p0 >> 8)   == code2)  sel[nt0][1] = (c1 >= 0.f) ? c1 : 0.2f * c1;
                if ((p1 & 0xFF) == code2)  sel[nt0][2] = (c2 >= 0.f) ? c2 : 0.2f * c2;
                if ((p1 >> 8)   == code2)  sel[nt0][3] = (c3 >= 0.f) ? c3 : 0.2f * c3;
                p0 = adjp[nt1 * 2]; p1 = adjp[nt1 * 2 + 1];
                if ((p0 & 0xFF) == code2)  sel[nt1][0] = (d0 >= 0.f) ? d0 : 0.2f * d0;
                if ((p0 >> 8)   == code2)  sel[nt1][1] = (d1 >= 0.f) ? d1 : 0.2f * d1;
                if ((p1 & 0xFF) == code2)  sel[nt1][2] = (d2 >= 0.f) ? d2 : 0.2f * d2;
                if ((p1 >> 8)   == code2)  sel[nt1][3] = (d3 >= 0.f) ? d3 : 0.2f * d3;
            }
        }

        // ===== online fragment softmax (single block exchange) =====
        float m0 = NEG_BIG, m1 = NEG_BIG;
        #pragma unroll
        for (int nt = 0; nt < 4; nt++) {
            m0 = fmaxf(m0, fmaxf(sel[nt][0], sel[nt][1]));
            m1 = fmaxf(m1, fmaxf(sel[nt][2], sel[nt][3]));
        }
        m0 = fmaxf(m0, __shfl_xor_sync(0xffffffffu, m0, 1));
        m0 = fmaxf(m0, __shfl_xor_sync(0xffffffffu, m0, 2));
        m1 = fmaxf(m1, __shfl_xor_sync(0xffffffffu, m1, 1));
        m1 = fmaxf(m1, __shfl_xor_sync(0xffffffffu, m1, 2));
        float s0 = 0.f, s1 = 0.f;
        #pragma unroll
        for (int nt = 0; nt < 4; nt++) {
            sel[nt][0] = __expf(sel[nt][0] - m0); s0 += sel[nt][0];
            sel[nt][1] = __expf(sel[nt][1] - m0); s0 += sel[nt][1];
            sel[nt][2] = __expf(sel[nt][2] - m1); s1 += sel[nt][2];
            sel[nt][3] = __expf(sel[nt][3] - m1); s1 += sel[nt][3];
        }
        s0 += __shfl_xor_sync(0xffffffffu, s0, 1);
        s0 += __shfl_xor_sync(0xffffffffu, s0, 2);
        s1 += __shfl_xor_sync(0xffffffffu, s1, 1);
        s1 += __shfl_xor_sync(0xffffffffu, s1, 2);
        if ((lane & 3) == 0) {
            PA[i0 * 2 + nhalf] = m0;  PB[i0 * 2 + nhalf] = s0;
            PA[(i0 + 8) * 2 + nhalf] = m1;  PB[(i0 + 8) * 2 + nhalf] = s1;
        }
        __syncthreads();
        float mg0 = fmaxf(PA[i0 * 2], PA[i0 * 2 + 1]);
        float mg1 = fmaxf(PA[(i0 + 8) * 2], PA[(i0 + 8) * 2 + 1]);
        float sg0 = PB[i0 * 2] * __expf(PA[i0 * 2] - mg0)
                  + PB[i0 * 2 + 1] * __expf(PA[i0 * 2 + 1] - mg0);
        float sg1 = PB[(i0 + 8) * 2] * __expf(PA[(i0 + 8) * 2] - mg1)
                  + PB[(i0 + 8) * 2 + 1] * __expf(PA[(i0 + 8) * 2 + 1] - mg1);
        float inv0 = __expf(m0 - mg0) / sg0;
        float inv1 = __expf(m1 - mg1) / sg1;

        // ===== write ATT tile =====
        #pragma unroll
        for (int nt = 0; nt < 4; nt++) {
            int j0 = N0 + nt * 8 + ((lane & 3) << 1);
            uint32_t hi, lo;
            cvt_hilo(make_float2(sel[nt][0] * inv0, sel[nt][1] * inv0), hi, lo);
            int off = i0 * ATT_S + j0 * 2;
            *reinterpret_cast<uint32_t*>(YT + off)            = hi;
            *reinterpret_cast<uint32_t*>(YT + ATT_HALF + off) = lo;
            cvt_hilo(make_float2(sel[nt][2] * inv1, sel[nt][3] * inv1), hi, lo);
            off = (i0 + 8) * ATT_S + j0 * 2;
            *reinterpret_cast<uint32_t*>(YT + off)            = hi;
            *reinterpret_cast<uint32_t*>(YT + ATT_HALF + off) = lo;
        }
        __syncthreads();

        // ===== T = att @ S (A from ATT, B = X^T, x4.trans) =====
        {
            uint32_t aah[16], aal[16];
            uint32_t tabase = YH + (uint32_t)(R0 + (lane & 7) + ((m4 & 1) << 3)) * ATT_S
                            + ((m4 >> 1) << 4);
            #pragma unroll
            for (int kt = 0; kt < 4; kt++) {
                LDSM4(&aah[kt * 4], tabase + kt * 32);
                LDSM4(&aal[kt * 4], tabase + ATT_HALF + kt * 32);
            }
            const int N0d = nhalf * 64;
            const uint32_t t4base = XH + (uint32_t)(lane & 15) * TS
                                  + (uint32_t)N0d * 2 + ((lane >> 4) & 1) * 16;
            float tc[8][4];
            #pragma unroll
            for (int nt = 0; nt < 8; nt++)
                #pragma unroll
                for (int q = 0; q < 4; q++) tc[nt][q] = 0.f;
            #pragma unroll
            for (int ntp = 0; ntp < 4; ntp++) {
                #pragma unroll
                for (int kt = 0; kt < 4; kt++) {
                    uint32_t bq[4], bql[4];
                    uint32_t ba = t4base + (uint32_t)(kt * 16) * TS + ntp * 32;
                    LDSM4T(bq, ba);
                    LDSM4T(bql, ba + THALF);
                    int n0 = 2 * ntp, n1 = 2 * ntp + 1;
                    MMA16816(tc[n0][0], tc[n0][1], tc[n0][2], tc[n0][3], &aah[kt * 4], bq[0], bq[1]);
                    MMA16816(tc[n0][0], tc[n0][1], tc[n0][2], tc[n0][3], &aah[kt * 4], bql[0], bql[1]);
                    MMA16816(tc[n0][0], tc[n0][1], tc[n0][2], tc[n0][3], &aal[kt * 4], bq[0], bq[1]);
                    MMA16816(tc[n1][0], tc[n1][1], tc[n1][2], tc[n1][3], &aah[kt * 4], bq[2], bq[3]);
                    MMA16816(tc[n1][0], tc[n1][1], tc[n1][2], tc[n1][3], &aah[kt * 4], bql[2], bql[3]);
                    MMA16816(tc[n1][0], tc[n1][1], tc[n1][2], tc[n1][3], &aal[kt * 4], bq[2], bq[3]);
                }
            }

            float pa0 = 0.f, pa1 = 0.f;
            #pragma unroll
            for (int nt = 0; nt < 8; nt++) {
                int d0 = N0d + nt * 8 + ((lane & 3) << 1);
                float2 va = *reinterpret_cast<const float2*>(&V2A[d0]);
                pa0 += tc[nt][0] * va.x + tc[nt][1] * va.y;
                pa1 += tc[nt][2] * va.x + tc[nt][3] * va.y;
            }
            pa0 += __shfl_xor_sync(0xffffffffu, pa0, 1);
            pa0 += __shfl_xor_sync(0xffffffffu, pa0, 2);
            pa1 += __shfl_xor_sync(0xffffffffu, pa1, 1);
            pa1 += __shfl_xor_sync(0xffffffffu, pa1, 2);
            if ((lane & 3) == 0) { PA[i0 * 2 + nhalf] = pa0; PA[(i0 + 8) * 2 + nhalf] = pa1; }
            __syncthreads();
            float al0 = (PA[i0 * 2] + PA[i0 * 2 + 1]) * RSQ;
            float al1 = (PA[(i0 + 8) * 2] + PA[(i0 + 8) * 2 + 1]) * RSQ;

            float pb0 = 0.f, pb1 = 0.f;
            #pragma unroll
            for (int nt = 0; nt < 8; nt++) {
                int d0 = N0d + nt * 8 + ((lane & 3) << 1);
                float2 st = *reinterpret_cast<const float2*>(&STAR[d0]);
                float2 vb = *reinterpret_cast<const float2*>(&V2B[d0]);
                float n0x = (1.f - al0) * tc[nt][0] + al0 * st.x;
                float n0y = (1.f - al0) * tc[nt][1] + al0 * st.y;
                float n1x = (1.f - al1) * tc[nt][2] + al1 * st.x;
                float n1y = (1.f - al1) * tc[nt][3] + al1 * st.y;
                *reinterpret_cast<float2*>(&S[i0 * NPAD + d0])       = make_float2(n0x, n0y);
                *reinterpret_cast<float2*>(&S[(i0 + 8) * NPAD + d0]) = make_float2(n1x, n1y);
                uint32_t hi, lo;
                int off = i0 * TS + d0 * 2;
                cvt_hilo(make_float2(n0x, n0y), hi, lo);
                *reinterpret_cast<uint32_t*>(XT + off)         = hi;
                *reinterpret_cast<uint32_t*>(XT + THALF + off) = lo;
                off = (i0 + 8) * TS + d0 * 2;
                cvt_hilo(make_float2(n1x, n1y), hi, lo);
                *reinterpret_cast<uint32_t*>(XT + off)         = hi;
                *reinterpret_cast<uint32_t*>(XT + THALF + off) = lo;
                pb0 += n0x * vb.x + n0y * vb.y;
                pb1 += n1x * vb.x + n1y * vb.y;
            }
            pb0 += __shfl_xor_sync(0xffffffffu, pb0, 1);
            pb0 += __shfl_xor_sync(0xffffffffu, pb0, 2);
            pb1 += __shfl_xor_sync(0xffffffffu, pb1, 1);
            pb1 += __shfl_xor_sync(0xffffffffu, pb1, 2);
            if ((lane & 3) == 0) { PB[i0 * 2 + nhalf] = pb0; PB[(i0 + 8) * 2 + nhalf] = pb1; }
        }
        __syncthreads();

        if (warp == 0) {
            float b0 = (MS[lane] == 0.f)      ? __int_as_float(0xff800000)
                                              : (PB[lane * 2] + PB[lane * 2 + 1]) * RSQ;
            float b1 = (MS[lane + 32] == 0.f) ? __int_as_float(0xff800000)
                                              : (PB[(lane + 32) * 2] + PB[(lane + 32) * 2 + 1]) * RSQ;
            float m = fmaxf(b0, b1);
            #pragma unroll
            for (int o = 16; o > 0; o >>= 1) m = fmaxf(m, __shfl_xor_sync(0xffffffffu, m, o));
            float e0 = __expf(b0 - m), e1 = __expf(b1 - m);
            float sE = e0 + e1;
            #pragma unroll
            for (int o = 16; o > 0; o >>= 1) sE += __shfl_xor_sync(0xffffffffu, sE, o);
            float inv = 1.f / sE;
            BR[lane] = e0 * inv; BR[lane + 32] = e1 * inv;
        }
        __syncthreads();
        if (tid < 128) {
            float acc = 0.f;
            #pragma unroll 8
            for (int j = 0; j < 64; j++) acc += BR[j] * S[j * NPAD + tid];
            STAR[tid] = acc;
        }
        __syncthreads();
    }

    // ===== gate: half-scoped W staging =====
    {
        char* WT = YT;
        const uint32_t WTH = YH;
        const int N0g = nhalf * 64;
        const uint32_t gbase4 = WTH + (uint32_t)(N0g + rsel4) * GWS + csel4;
        float acc[8][4];
        #pragma unroll
        for (int nt = 0; nt < 8; nt++)
            #pragma unroll
            for (int q = 0; q < 4; q++) acc[nt][q] = 0.f;

        for (int chunk = 0; chunk < 4; chunk++) {
            const int c0 = chunk * 64;
            if (chunk > 0) BARH(nhalf);           // this half's W reads done (chunk 0 guarded by prior block sync)
            // stage this half's W rows [N0g, N0g+64)
            for (int idx = t128; idx < 1024; idx += 128) {
                int o = N0g + (idx >> 4), p4 = idx & 15;
                float4 w = __ldg(reinterpret_cast<const float4*>(&wlin[o * 256 + c0 + p4 * 4]));
                uint32_t h0, l0, h1, l1;
                cvt_hilo(make_float2(w.x, w.y), h0, l0);
                cvt_hilo(make_float2(w.z, w.w), h1, l1);
                *reinterpret_cast<uint2*>(WT + o * GWS + p4 * 8)          = make_uint2(h0, h1);
                *reinterpret_cast<uint2*>(WT + GWHALF + o * GWS + p4 * 8) = make_uint2(l0, l1);
            }
            BARH(nhalf);
            const bool fh2 = chunk < 2;
            const int cb = fh2 ? c0 : (c0 - 128);
            const int r0 = i0;
            #pragma unroll
            for (int kt = 0; kt < 4; kt++) {
                uint32_t fah[4], fal[4];
                if (fh2) {
                    int cc = cb + kt * 16 + ((lane & 3) << 1);
                    float2 x00 = __ldg(reinterpret_cast<const float2*>(&hg[r0 * 128 + cc]));
                    float2 x10 = __ldg(reinterpret_cast<const float2*>(&hg[(r0 + 8) * 128 + cc]));
                    float2 x01 = __ldg(reinterpret_cast<const float2*>(&hg[r0 * 128 + cc + 8]));
                    float2 x11 = __ldg(reinterpret_cast<const float2*>(&hg[(r0 + 8) * 128 + cc + 8]));
                    cvt_hilo(x00, fah[0], fal[0]);
                    cvt_hilo(x10, fah[1], fal[1]);
                    cvt_hilo(x01, fah[2], fal[2]);
                    cvt_hilo(x11, fah[3], fal[3]);
                } else {
                    uint32_t ab2 = abase + (uint32_t)(cb + kt * 16) * 2;
                    LDSM4(fah, ab2);
                    LDSM4(fal, ab2 + THALF);
                }
                #pragma unroll
                for (int ntp = 0; ntp < 4; ntp++) {
                    uint32_t bq[4], bql[4];
                    uint32_t ba = gbase4 + ntp * (16 * GWS) + kt * 32;
                    LDSM4(bq, ba);
                    LDSM4(bql, ba + GWHALF);
                    int n0 = 2 * ntp, n1 = 2 * ntp + 1;
                    MMA16816(acc[n0][0], acc[n0][1], acc[n0][2], acc[n0][3], fah, bq[0], bq[1]);
                    MMA16816(acc[n0][0], acc[n0][1], acc[n0][2], acc[n0][3], fah, bql[0], bql[1]);
                    MMA16816(acc[n0][0], acc[n0][1], acc[n0][2], acc[n0][3], fal, bq[0], bq[1]);
                    MMA16816(acc[n1][0], acc[n1][1], acc[n1][2], acc[n1][3], fah, bq[2], bq[3]);
                    MMA16816(acc[n1][0], acc[n1][1], acc[n1][2], acc[n1][3], fah, bql[2], bql[3]);
                    MMA16816(acc[n1][0], acc[n1][1], acc[n1][2], acc[n1][3], fal, bq[2], bq[3]);
                }
            }
        }

        float* ob = outp + (size_t)b * (NN * 128);
        const int r0 = i0;
        #pragma unroll
        for (int nt = 0; nt < 8; nt++) {
            int o0 = N0g + nt * 8 + ((lane & 3) << 1);
            float2 h0 = __ldg(reinterpret_cast<const float2*>(&hg[r0 * 128 + o0]));
            float2 s0v = *reinterpret_cast<const float2*>(&S[r0 * NPAD + o0]);
            float2 h1 = __ldg(reinterpret_cast<const float2*>(&hg[(r0 + 8) * 128 + o0]));
            float2 s1v = *reinterpret_cast<const float2*>(&S[(r0 + 8) * NPAD + o0]);
            float g00 = 1.f / (1.f + __expf(-acc[nt][0]));
            float g01 = 1.f / (1.f + __expf(-acc[nt][1]));
            float g10 = 1.f / (1.f + __expf(-acc[nt][2]));
            float g11 = 1.f / (1.f + __expf(-acc[nt][3]));
            float2 r0v, r1v;
            r0v.x = g00 * h0.x + (1.f - g00) * s0v.x;
            r0v.y = g01 * h0.y + (1.f - g01) * s0v.y;
            r1v.x = g10 * h1.x + (1.f - g10) * s1v.x;
            r1v.y = g11 * h1.y + (1.f - g11) * s1v.y;
            *reinterpret_cast<float2*>(&ob[r0 * 128 + o0])       = r0v;
            *reinterpret_cast<float2*>(&ob[(r0 + 8) * 128 + o0]) = r1v;
        }
    }
    if (tid < 128) starp[(size_t)b * 128 + tid] = STAR[tid];
}

extern "C" void kernel_launch(void* const* d_in, const int* in_sizes, int n_in,
                              void* d_out, int out_size) {
    float* outp  = (float*)d_out;
    float* starp = outp + (size_t)NB * NN * 128;

    prep_kernel<<<128, 256>>>((const float*)d_in[7], (const float*)d_in[8],
                              (const float*)d_in[9], (const float*)d_in[10]);
    cudaFuncSetAttribute(star_agg_kernel, cudaFuncAttributeMaxDynamicSharedMemorySize, SM_BYTES);
    star_agg_kernel<<<NB, 256, SM_BYTES>>>(
        (const float*)d_in[0], (const int*)d_in[1], (const float*)d_in[2],
        (const float*)d_in[3], (const float*)d_in[4], (const float*)d_in[5], (const float*)d_in[6],
        (const float*)d_in[11], outp, starp);
}

// round 17
// speedup vs baseline: 1.3517x; 1.0003x over previous
#include <cuda_runtime.h>
#include <cuda_bf16.h>
#include <cstdint>

#define NB   2048
#define NN   64
#define NPAD 132
#define NEG_BIG (-9000000000000000.0f)

#define OFF_S    0
#define OFF_X    8448
#define OFF_Y    17152
#define OFF_A    25856
#define OFF_STAR 26368
#define OFF_V2A  26496
#define OFF_V2B  26624
#define OFF_MS   26752
#define OFF_BR   26816
#define OFF_PA   26880
#define OFF_PB   27008
#define SM_FLOATS 27136
#define SM_BYTES (SM_FLOATS*4 + 64*68)

#define TS    272
#define THALF 17408
#define ATT_S 144
#define ATT_HALF 9216
#define GWS   144
#define GWHALF (128*144)

__device__ float g_M1T[16384];   // (q1 @ k1^T)^T — coalesced column access
__device__ float g_M2T[16384];   // (k2 @ q2^T)^T

__device__ __forceinline__ uint32_t smem_u32(const void* p) {
    uint32_t a;
    asm("{ .reg .u64 t; cvta.to.shared.u64 t, %1; cvt.u32.u64 %0, t; }" : "=r"(a) : "l"(p));
    return a;
}
__device__ __forceinline__ uint32_t pack_bf2(__nv_bfloat16 a, __nv_bfloat16 b) {
    __nv_bfloat162 v = __halves2bfloat162(a, b);
    return *reinterpret_cast<uint32_t*>(&v);
}
__device__ __forceinline__ void cvt_hilo(float2 v, uint32_t& hi, uint32_t& lo) {
    __nv_bfloat16 h0 = __float2bfloat16_rn(v.x), h1 = __float2bfloat16_rn(v.y);
    hi = pack_bf2(h0, h1);
    lo = pack_bf2(__float2bfloat16_rn(v.x - __bfloat162float(h0)),
                  __float2bfloat16_rn(v.y - __bfloat162float(h1)));
}

#define LDSM4(r, addr) \
    asm volatile("ldmatrix.sync.aligned.m8n8.x4.shared.b16 {%0,%1,%2,%3}, [%4];" \
        : "=r"((r)[0]), "=r"((r)[1]), "=r"((r)[2]), "=r"((r)[3]) : "r"(addr))
#define LDSM4T(r, addr) \
    asm volatile("ldmatrix.sync.aligned.m8n8.x4.trans.shared.b16 {%0,%1,%2,%3}, [%4];" \
        : "=r"((r)[0]), "=r"((r)[1]), "=r"((r)[2]), "=r"((r)[3]) : "r"(addr))
#define MMA16816(c0,c1,c2,c3, a, b0,b1) \
    asm volatile("mma.sync.aligned.m16n8k16.row.col.f32.bf16.bf16.f32 " \
        "{%0,%1,%2,%3}, {%4,%5,%6,%7}, {%8,%9}, {%0,%1,%2,%3};" \
        : "+f"(c0), "+f"(c1), "+f"(c2), "+f"(c3) \
        : "r"((a)[0]), "r"((a)[1]), "r"((a)[2]), "r"((a)[3]), "r"(b0), "r"(b1))
#define BARH(h)  asm volatile("bar.sync %0, 128;" :: "r"(1 + (h)) : "memory")
#define BARP(m)  asm volatile("bar.sync %0, 64;"  :: "r"(3 + (m)) : "memory")

// full-tile build (init only): thread owns col quad d=(tid&31)*4
__device__ __forceinline__ void build_tile(const float* S, char* tile, int tid) {
    const int d = (tid & 31) << 2;
    const int rb = tid >> 5;
    #pragma unroll
    for (int i = 0; i < 8; i++) {
        int row = rb + i * 8;
        float4 sv = *reinterpret_cast<const float4*>(&S[row * NPAD + d]);
        uint32_t h0, l0, h1, l1;
        cvt_hilo(make_float2(sv.x, sv.y), h0, l0);
        cvt_hilo(make_float2(sv.z, sv.w), h1, l1);
        int off = row * TS + d * 2;
        *reinterpret_cast<uint2*>(tile + off)         = make_uint2(h0, h1);
        *reinterpret_cast<uint2*>(tile + THALF + off) = make_uint2(l0, l1);
    }
}

// half-tile build: half hh builds rows [hh*32, hh*32+32), t128 = tid&127
__device__ __forceinline__ void build_tile_half(const float* S, const float* vec,
                                                char* tile, int t128, int hh) {
    const int d = (t128 & 31) << 2;
    const int rb = hh * 32 + (t128 >> 5);
    float4 av = *reinterpret_cast<const float4*>(&vec[d]);
    #pragma unroll
    for (int i = 0; i < 8; i++) {
        int row = rb + i * 4;
        float4 sv = *reinterpret_cast<const float4*>(&S[row * NPAD + d]);
        sv.x *= av.x; sv.y *= av.y; sv.z *= av.z; sv.w *= av.w;
        uint32_t h0, l0, h1, l1;
        cvt_hilo(make_float2(sv.x, sv.y), h0, l0);
        cvt_hilo(make_float2(sv.z, sv.w), h1, l1);
        int off = row * TS + d * 2;
        *reinterpret_cast<uint2*>(tile + off)         = make_uint2(h0, h1);
        *reinterpret_cast<uint2*>(tile + THALF + off) = make_uint2(l0, l1);
    }
}

__global__ void prep_kernel(const float* __restrict__ q1, const float* __restrict__ k1,
                            const float* __restrict__ q2, const float* __restrict__ k2) {
    int o = blockIdx.x * 256 + threadIdx.x;
    int m = o >> 14, idx = o & 16383;
    int t = idx >> 7, c = idx & 127;
    const float* X = m ? k2 : q1;
    const float* Y = m ? q2 : k1;
    float acc = 0.f;
    const float4* xr = reinterpret_cast<const float4*>(X + t * 128);
    const float4* yr = reinterpret_cast<const float4*>(Y + c * 128);
    #pragma unroll 8
    for (int d = 0; d < 32; d++) {
        float4 xv = xr[d], yv = yr[d];
        acc += xv.x * yv.x + xv.y * yv.y + xv.z * yv.z + xv.w * yv.w;
    }
    (m ? g_M2T : g_M1T)[c * 128 + t] = acc;
}

__global__ void __launch_bounds__(256, 2)
star_agg_kernel(const float* __restrict__ hidden, const int* __restrict__ adj,
                const float* __restrict__ mask,
                const float* __restrict__ a0, const float* __restrict__ a1,
                const float* __restrict__ a2, const float* __restrict__ a3,
                const float* __restrict__ wlin,
                float* __restrict__ outp, float* __restrict__ starp)
{
    extern __shared__ float sm[];
    float* S    = sm + OFF_S;
    float* A    = sm + OFF_A;
    float* STAR = sm + OFF_STAR;
    float* V2A  = sm + OFF_V2A;
    float* V2B  = sm + OFF_V2B;
    float* MS   = sm + OFF_MS;
    float* BR   = sm + OFF_BR;
    float* PA   = sm + OFF_PA;
    float* PB   = sm + OFF_PB;
    char*  XT   = (char*)(sm + OFF_X);
    char*  YT   = (char*)(sm + OFF_Y);
    unsigned char* ADJ = (unsigned char*)(sm + SM_FLOATS);  // [i][j] stride 68

    const int tid = threadIdx.x, lane = tid & 31, warp = tid >> 5, b = blockIdx.x;
    const int t128 = tid & 127;
    const uint32_t smb = smem_u32(sm);
    const uint32_t XH = smb + OFF_X * 4;
    const uint32_t YH = smb + OFF_Y * 4;
    const float* hg = hidden + (size_t)b * (NN * 128);
    const int*   ag = adj + (size_t)b * (NN * NN);

    for (int idx = tid; idx < NN * 32; idx += 256) {
        int i = idx >> 5, c4 = (idx & 31) << 2;
        *reinterpret_cast<float4*>(&S[i * NPAD + c4]) = reinterpret_cast<const float4*>(hg)[idx];
    }
    for (int idx = tid; idx < NN * NN; idx += 256)
        ADJ[(idx >> 6) * 68 + (idx & 63)] = (unsigned char)ag[idx];
    if (tid < 128) {
        A[tid] = a0[tid]; A[128 + tid] = a1[tid];
        A[256 + tid] = a2[tid]; A[384 + tid] = a3[tid];
    }
    if (tid < 64) MS[tid] = mask[b * NN + tid];
    __syncthreads();
    build_tile(S, XT, tid);
    if (tid < 128) {
        float acc = 0.f, msum = 0.f;
        #pragma unroll 8
        for (int i = 0; i < NN; i++) { acc += S[i * NPAD + tid] * MS[i]; msum += MS[i]; }
        STAR[tid] = acc / msum;
    }
    __syncthreads();

    const float RSQ = 0.088388347648318447f;
    const int mstrip = warp & 3, nhalf = warp >> 2;   // nhalf == tid>>7
    const int R0 = mstrip * 16, N0 = nhalf * 32;
    const int g = lane >> 2, i0 = R0 + g;
    const int m4 = lane >> 3;
    const uint32_t abase = XH + (uint32_t)(R0 + (lane & 7) + ((m4 & 1) << 3)) * TS
                         + ((m4 >> 1) << 4);
    const int rsel4 = ((lane >> 4) & 1) * 8 + (lane & 7);
    const int csel4 = ((lane >> 3) & 1) * 16;
    const uint32_t bbase4 = YH + (uint32_t)(N0 + rsel4) * TS + csel4;

    unsigned short adjp[8];
    #pragma unroll
    for (int nt = 0; nt < 4; nt++) {
        int j0 = N0 + nt * 8 + ((lane & 3) << 1);
        adjp[nt * 2]     = *reinterpret_cast<const unsigned short*>(&ADJ[i0 * 68 + j0]);
        adjp[nt * 2 + 1] = *reinterpret_cast<const unsigned short*>(&ADJ[(i0 + 8) * 68 + j0]);
    }

    for (int step = 0; step < 2; step++) {
        // ===== star matvecs (coalesced, parallel pairs) =====
        {
            const float* MT = nhalf ? g_M2T : g_M1T;
            float* V2g = nhalf ? V2B : V2A;
            float s0 = 0.f, s1 = 0.f, s2 = 0.f, s3 = 0.f;
            #pragma unroll 8
            for (int c = 0; c < 128; c += 4) {
                s0 += STAR[c]     * MT[c * 128 + t128];
                s1 += STAR[c + 1] * MT[(c + 1) * 128 + t128];
                s2 += STAR[c + 2] * MT[(c + 2) * 128 + t128];
                s3 += STAR[c + 3] * MT[(c + 3) * 128 + t128];
            }
            V2g[t128] = (s0 + s1) + (s2 + s3);
        }

        // ===== A frags (X tile, current S) =====
        uint32_t ah[32], al[32];
        #pragma unroll
        for (int kt = 0; kt < 8; kt++) {
            LDSM4(&ah[kt * 4], abase + kt * 32);
            LDSM4(&al[kt * 4], abase + THALF + kt * 32);
        }

        // ===== e-logits: half-scoped Y build/consume pipeline =====
        float sel[4][4];
        #pragma unroll
        for (int nt = 0; nt < 4; nt++)
            #pragma unroll
            for (int q = 0; q < 4; q++) sel[nt][q] = NEG_BIG;
        for (int k = 0; k < 4; k++) {
            if (k > 0) BARH(nhalf);               // this half's MMA reads of Y rows done
            build_tile_half(S, A + k * 128, YT, t128, nhalf);
            BARH(nhalf);                          // this half's Y rows ready
            const unsigned short code2 = (unsigned short)(k + 1);
            #pragma unroll
            for (int ntp = 0; ntp < 2; ntp++) {
                float c0 = 0.f, c1 = 0.f, c2 = 0.f, c3 = 0.f;
                float d0 = 0.f, d1 = 0.f, d2 = 0.f, d3 = 0.f;
                #pragma unroll
                for (int kt = 0; kt < 8; kt++) {
                    uint32_t bq[4], bql[4];
                    uint32_t ba = bbase4 + ntp * (16 * TS) + kt * 32;
                    LDSM4(bq, ba);
                    LDSM4(bql, ba + THALF);
                    MMA16816(c0, c1, c2, c3, &ah[kt * 4], bq[0], bq[1]);
                    MMA16816(c0, c1, c2, c3, &ah[kt * 4], bql[0], bql[1]);
                    MMA16816(c0, c1, c2, c3, &al[kt * 4], bq[0], bq[1]);
                    MMA16816(d0, d1, d2, d3, &ah[kt * 4], bq[2], bq[3]);
                    MMA16816(d0, d1, d2, d3, &ah[kt * 4], bql[2], bql[3]);
                    MMA16816(d0, d1, d2, d3, &al[kt * 4], bq[2], bq[3]);
                }
                int nt0 = 2 * ntp, nt1 = 2 * ntp + 1;
                unsigned short p0 = adjp[nt0 * 2], p1 = adjp[nt0 * 2 + 1];
                if ((p0 & 0xFF) == code2)  sel[nt0][0] = (c0 >= 0.f) ? c0 : 0.2f * c0;
                if ((p0 >> 8)   == code2)  sel[nt0][1] = (c1 >= 0.f) ? c1 : 0.2f * c1;
                if ((p1 & 0xFF) == code2)  sel[nt0][2] = (c2 >= 0.f) ? c2 : 0.2f * c2;
                if ((p1 >> 8)   == code2)  sel[nt0][3] = (c3 >= 0.f) ? c3 : 0.2f * c3;
                p0 = adjp[nt1 * 2]; p1 = adjp[nt1 * 2 + 1];
                if ((p0 & 0xFF) == code2)  sel[nt1][0] = (d0 >= 0.f) ? d0 : 0.2f * d0;
                if ((p0 >> 8)   == code2)  sel[nt1][1] = (d1 >= 0.f) ? d1 : 0.2f * d1;
                if ((p1 & 0xFF) == code2)  sel[nt1][2] = (d2 >= 0.f) ? d2 : 0.2f * d2;
                if ((p1 >> 8)   == code2)  sel[nt1][3] = (d3 >= 0.f) ? d3 : 0.2f * d3;
            }
        }

        // ===== online fragment softmax (single block exchange; also orders
        //        all Y reads before ATT writes into the aliased region) =====
        float m0 = NEG_BIG, m1 = NEG_BIG;
        #pragma unroll
        for (int nt = 0; nt < 4; nt++) {
            m0 = fmaxf(m0, fmaxf(sel[nt][0], sel[nt][1]));
            m1 = fmaxf(m1, fmaxf(sel[nt][2], sel[nt][3]));
        }
        m0 = fmaxf(m0, __shfl_xor_sync(0xffffffffu, m0, 1));
        m0 = fmaxf(m0, __shfl_xor_sync(0xffffffffu, m0, 2));
        m1 = fmaxf(m1, __shfl_xor_sync(0xffffffffu, m1, 1));
        m1 = fmaxf(m1, __shfl_xor_sync(0xffffffffu, m1, 2));
        float s0 = 0.f, s1 = 0.f;
        #pragma unroll
        for (int nt = 0; nt < 4; nt++) {
            sel[nt][0] = __expf(sel[nt][0] - m0); s0 += sel[nt][0];
            sel[nt][1] = __expf(sel[nt][1] - m0); s0 += sel[nt][1];
            sel[nt][2] = __expf(sel[nt][2] - m1); s1 += sel[nt][2];
            sel[nt][3] = __expf(sel[nt][3] - m1); s1 += sel[nt][3];
        }
        s0 += __shfl_xor_sync(0xffffffffu, s0, 1);
        s0 += __shfl_xor_sync(0xffffffffu, s0, 2);
        s1 += __shfl_xor_sync(0xffffffffu, s1, 1);
        s1 += __shfl_xor_sync(0xffffffffu, s1, 2);
        if ((lane & 3) == 0) {
            PA[i0 * 2 + nhalf] = m0;  PB[i0 * 2 + nhalf] = s0;
            PA[(i0 + 8) * 2 + nhalf] = m1;  PB[(i0 + 8) * 2 + nhalf] = s1;
        }
        __syncthreads();
        float mg0 = fmaxf(PA[i0 * 2], PA[i0 * 2 + 1]);
        float mg1 = fmaxf(PA[(i0 + 8) * 2], PA[(i0 + 8) * 2 + 1]);
        float sg0 = PB[i0 * 2] * __expf(PA[i0 * 2] - mg0)
                  + PB[i0 * 2 + 1] * __expf(PA[i0 * 2 + 1] - mg0);
        float sg1 = PB[(i0 + 8) * 2] * __expf(PA[(i0 + 8) * 2] - mg1)
                  + PB[(i0 + 8) * 2 + 1] * __expf(PA[(i0 + 8) * 2 + 1] - mg1);
        float inv0 = __expf(m0 - mg0) / sg0;
        float inv1 = __expf(m1 - mg1) / sg1;

        // ===== write ATT tile (mstrip-pair rows) =====
        #pragma unroll
        for (int nt = 0; nt < 4; nt++) {
            int j0 = N0 + nt * 8 + ((lane & 3) << 1);
            uint32_t hi, lo;
            cvt_hilo(make_float2(sel[nt][0] * inv0, sel[nt][1] * inv0), hi, lo);
            int off = i0 * ATT_S + j0 * 2;
            *reinterpret_cast<uint32_t*>(YT + off)            = hi;
            *reinterpret_cast<uint32_t*>(YT + ATT_HALF + off) = lo;
            cvt_hilo(make_float2(sel[nt][2] * inv1, sel[nt][3] * inv1), hi, lo);
            off = (i0 + 8) * ATT_S + j0 * 2;
            *reinterpret_cast<uint32_t*>(YT + off)            = hi;
            *reinterpret_cast<uint32_t*>(YT + ATT_HALF + off) = lo;
        }
        BARP(mstrip);   // ATT rows [R0,R0+16) written only by this mstrip pair

        // ===== T = att @ S (A from ATT, B = X^T, x4.trans) =====
        {
            uint32_t aah[16], aal[16];
            uint32_t tabase = YH + (uint32_t)(R0 + (lane & 7) + ((m4 & 1) << 3)) * ATT_S
                            + ((m4 >> 1) << 4);
            #pragma unroll
            for (int kt = 0; kt < 4; kt++) {
                LDSM4(&aah[kt * 4], tabase + kt * 32);
                LDSM4(&aal[kt * 4], tabase + ATT_HALF + kt * 32);
            }
            const int N0d = nhalf * 64;
            const uint32_t t4base = XH + (uint32_t)(lane & 15) * TS
                                  + (uint32_t)N0d * 2 + ((lane >> 4) & 1) * 16;
            float tc[8][4];
            #pragma unroll
            for (int nt = 0; nt < 8; nt++)
                #pragma unroll
                for (int q = 0; q < 4; q++) tc[nt][q] = 0.f;
            #pragma unroll
            for (int ntp = 0; ntp < 4; ntp++) {
                #pragma unroll
                for (int kt = 0; kt < 4; kt++) {
                    uint32_t bq[4], bql[4];
                    uint32_t ba = t4base + (uint32_t)(kt * 16) * TS + ntp * 32;
                    LDSM4T(bq, ba);
                    LDSM4T(bql, ba + THALF);
                    int n0 = 2 * ntp, n1 = 2 * ntp + 1;
                    MMA16816(tc[n0][0], tc[n0][1], tc[n0][2], tc[n0][3], &aah[kt * 4], bq[0], bq[1]);
                    MMA16816(tc[n0][0], tc[n0][1], tc[n0][2], tc[n0][3], &aah[kt * 4], bql[0], bql[1]);
                    MMA16816(tc[n0][0], tc[n0][1], tc[n0][2], tc[n0][3], &aal[kt * 4], bq[0], bq[1]);
                    MMA16816(tc[n1][0], tc[n1][1], tc[n1][2], tc[n1][3], &aah[kt * 4], bq[2], bq[3]);
                    MMA16816(tc[n1][0], tc[n1][1], tc[n1][2], tc[n1][3], &aah[kt * 4], bql[2], bql[3]);
                    MMA16816(tc[n1][0], tc[n1][1], tc[n1][2], tc[n1][3], &aal[kt * 4], bq[2], bq[3]);
                }
            }

            float pa0 = 0.f, pa1 = 0.f;
            #pragma unroll
            for (int nt = 0; nt < 8; nt++) {
                int d0 = N0d + nt * 8 + ((lane & 3) << 1);
                float2 va = *reinterpret_cast<const float2*>(&V2A[d0]);
                pa0 += tc[nt][0] * va.x + tc[nt][1] * va.y;
                pa1 += tc[nt][2] * va.x + tc[nt][3] * va.y;
            }
            pa0 += __shfl_xor_sync(0xffffffffu, pa0, 1);
            pa0 += __shfl_xor_sync(0xffffffffu, pa0, 2);
            pa1 += __shfl_xor_sync(0xffffffffu, pa1, 1);
            pa1 += __shfl_xor_sync(0xffffffffu, pa1, 2);
            if ((lane & 3) == 0) { PA[i0 * 2 + nhalf] = pa0; PA[(i0 + 8) * 2 + nhalf] = pa1; }
            __syncthreads();    // PA exchange + guards X writes below vs X reads above
            float al0 = (PA[i0 * 2] + PA[i0 * 2 + 1]) * RSQ;
            float al1 = (PA[(i0 + 8) * 2] + PA[(i0 + 8) * 2 + 1]) * RSQ;

            float pb0 = 0.f, pb1 = 0.f;
            #pragma unroll
            for (int nt = 0; nt < 8; nt++) {
                int d0 = N0d + nt * 8 + ((lane & 3) << 1);
                float2 st = *reinterpret_cast<const float2*>(&STAR[d0]);
                float2 vb = *reinterpret_cast<const float2*>(&V2B[d0]);
                float n0x = (1.f - al0) * tc[nt][0] + al0 * st.x;
                float n0y = (1.f - al0) * tc[nt][1] + al0 * st.y;
                float n1x = (1.f - al1) * tc[nt][2] + al1 * st.x;
                float n1y = (1.f - al1) * tc[nt][3] + al1 * st.y;
                *reinterpret_cast<float2*>(&S[i0 * NPAD + d0])       = make_float2(n0x, n0y);
                *reinterpret_cast<float2*>(&S[(i0 + 8) * NPAD + d0]) = make_float2(n1x, n1y);
                uint32_t hi, lo;
                int off = i0 * TS + d0 * 2;
                cvt_hilo(make_float2(n0x, n0y), hi, lo);
                *reinterpret_cast<uint32_t*>(XT + off)         = hi;
                *reinterpret_cast<uint32_t*>(XT + THALF + off) = lo;
                off = (i0 + 8) * TS + d0 * 2;
                cvt_hilo(make_float2(n1x, n1y), hi, lo);
                *reinterpret_cast<uint32_t*>(XT + off)         = hi;
                *reinterpret_cast<uint32_t*>(XT + THALF + off) = lo;
                pb0 += n0x * vb.x + n0y * vb.y;
                pb1 += n1x * vb.x + n1y * vb.y;
            }
            pb0 += __shfl_xor_sync(0xffffffffu, pb0, 1);
            pb0 += __shfl_xor_sync(0xffffffffu, pb0, 2);
            pb1 += __shfl_xor_sync(0xffffffffu, pb1, 1);
            pb1 += __shfl_xor_sync(0xffffffffu, pb1, 2);
            if ((lane & 3) == 0) { PB[i0 * 2 + nhalf] = pb0; PB[(i0 + 8) * 2 + nhalf] = pb1; }
        }
        __syncthreads();

        if (warp == 0) {
            float b0 = (MS[lane] == 0.f)      ? __int_as_float(0xff800000)
                                              : (PB[lane * 2] + PB[lane * 2 + 1]) * RSQ;
            float b1 = (MS[lane + 32] == 0.f) ? __int_as_float(0xff800000)
                                              : (PB[(lane + 32) * 2] + PB[(lane + 32) * 2 + 1]) * RSQ;
            float m = fmaxf(b0, b1);
            #pragma unroll
            for (int o = 16; o > 0; o >>= 1) m = fmaxf(m, __shfl_xor_sync(0xffffffffu, m, o));
            float e0 = __expf(b0 - m), e1 = __expf(b1 - m);
            float sE = e0 + e1;
            #pragma unroll
            for (int o = 16; o > 0; o >>= 1) sE += __shfl_xor_sync(0xffffffffu, sE, o);
            float inv = 1.f / sE;
            BR[lane] = e0 * inv; BR[lane + 32] = e1 * inv;
        }
        __syncthreads();
        if (tid < 128) {
            float acc = 0.f;
            #pragma unroll 8
            for (int j = 0; j < 64; j++) acc += BR[j] * S[j * NPAD + tid];
            STAR[tid] = acc;
        }
        __syncthreads();
    }

    // ===== gate: half-scoped W staging =====
    {
        char* WT = YT;
        const uint32_t WTH = YH;
        const int N0g = nhalf * 64;
        const uint32_t gbase4 = WTH + (uint32_t)(N0g + rsel4) * GWS + csel4;
        float acc[8][4];
        #pragma unroll
        for (int nt = 0; nt < 8; nt++)
            #pragma unroll
            for (int q = 0; q < 4; q++) acc[nt][q] = 0.f;

        for (int chunk = 0; chunk < 4; chunk++) {
            const int c0 = chunk * 64;
            if (chunk > 0) BARH(nhalf);
            for (int idx = t128; idx < 1024; idx += 128) {
                int o = N0g + (idx >> 4), p4 = idx & 15;
                float4 w = __ldg(reinterpret_cast<const float4*>(&wlin[o * 256 + c0 + p4 * 4]));
                uint32_t h0, l0, h1, l1;
                cvt_hilo(make_float2(w.x, w.y), h0, l0);
                cvt_hilo(make_float2(w.z, w.w), h1, l1);
                *reinterpret_cast<uint2*>(WT + o * GWS + p4 * 8)          = make_uint2(h0, h1);
                *reinterpret_cast<uint2*>(WT + GWHALF + o * GWS + p4 * 8) = make_uint2(l0, l1);
            }
            BARH(nhalf);
            const bool fh2 = chunk < 2;
            const int cb = fh2 ? c0 : (c0 - 128);
            const int r0 = i0;
            #pragma unroll
            for (int kt = 0; kt < 4; kt++) {
                uint32_t fah[4], fal[4];
                if (fh2) {
                    int cc = cb + kt * 16 + ((lane & 3) << 1);
                    float2 x00 = __ldg(reinterpret_cast<const float2*>(&hg[r0 * 128 + cc]));
                    float2 x10 = __ldg(reinterpret_cast<const float2*>(&hg[(r0 + 8) * 128 + cc]));
                    float2 x01 = __ldg(reinterpret_cast<const float2*>(&hg[r0 * 128 + cc + 8]));
                    float2 x11 = __ldg(reinterpret_cast<const float2*>(&hg[(r0 + 8) * 128 + cc + 8]));
                    cvt_hilo(x00, fah[0], fal[0]);
                    cvt_hilo(x10, fah[1], fal[1]);
                    cvt_hilo(x01, fah[2], fal[2]);
                    cvt_hilo(x11, fah[3], fal[3]);
                } else {
                    uint32_t ab2 = abase + (uint32_t)(cb + kt * 16) * 2;
                    LDSM4(fah, ab2);
                    LDSM4(fal, ab2 + THALF);
                }
                #pragma unroll
                for (int ntp = 0; ntp < 4; ntp++) {
                    uint32_t bq[4], bql[4];
                    uint32_t ba = gbase4 + ntp * (16 * GWS) + kt * 32;
                    LDSM4(bq, ba);
                    LDSM4(bql, ba + GWHALF);
                    int n0 = 2 * ntp, n1 = 2 * ntp + 1;
                    MMA16816(acc[n0][0], acc[n0][1], acc[n0][2], acc[n0][3], fah, bq[0], bq[1]);
                    MMA16816(acc[n0][0], acc[n0][1], acc[n0][2], acc[n0][3], fah, bql[0], bql[1]);
                    MMA16816(acc[n0][0], acc[n0][1], acc[n0][2], acc[n0][3], fal, bq[0], bq[1]);
                    MMA16816(acc[n1][0], acc[n1][1], acc[n1][2], acc[n1][3], fah, bq[2], bq[3]);
                    MMA16816(acc[n1][0], acc[n1][1], acc[n1][2], acc[n1][3], fah, bql[2], bql[3]);
                    MMA16816(acc[n1][0], acc[n1][1], acc[n1][2], acc[n1][3], fal, bq[2], bq[3]);
                }
            }
        }

        float* ob = outp + (size_t)b * (NN * 128);
        const int r0 = i0;
        #pragma unroll
        for (int nt = 0; nt < 8; nt++) {
            int o0 = N0g + nt * 8 + ((lane & 3) << 1);
            float2 h0 = __ldg(reinterpret_cast<const float2*>(&hg[r0 * 128 + o0]));
            float2 s0v = *reinterpret_cast<const float2*>(&S[r0 * NPAD + o0]);
            float2 h1 = __ldg(reinterpret_cast<const float2*>(&hg[(r0 + 8) * 128 + o0]));
            float2 s1v = *reinterpret_cast<const float2*>(&S[(r0 + 8) * NPAD + o0]);
            float g00 = 1.f / (1.f + __expf(-acc[nt][0]));
            float g01 = 1.f / (1.f + __expf(-acc[nt][1]));
            float g10 = 1.f / (1.f + __expf(-acc[nt][2]));
            float g11 = 1.f / (1.f + __expf(-acc[nt][3]));
            float2 r0v, r1v;
            r0v.x = g00 * h0.x + (1.f - g00) * s0v.x;
            r0v.y = g01 * h0.y + (1.f - g01) * s0v.y;
            r1v.x = g10 * h1.x + (1.f - g10) * s1v.x;
            r1v.y = g11 * h1.y + (1.f - g11) * s1v.y;
            *reinterpret_cast<float2*>(&ob[r0 * 128 + o0])       = r0v;
            *reinterpret_cast<float2*>(&ob[(r0 + 8) * 128 + o0]) = r1v;
        }
    }
    if (tid < 128) starp[(size_t)b * 128 + tid] = STAR[tid];
}

extern "C" void kernel_launch(void* const* d_in, const int* in_sizes, int n_in,
                              void* d_out, int out_size) {
    float* outp  = (float*)d_out;
    float* starp = outp + (size_t)NB * NN * 128;

    prep_kernel<<<128, 256>>>((const float*)d_in[7], (const float*)d_in[8],
                              (const float*)d_in[9], (const float*)d_in[10]);
    cudaFuncSetAttribute(star_agg_kernel, cudaFuncAttributeMaxDynamicSharedMemorySize, SM_BYTES);
    star_agg_kernel<<<NB, 256, SM_BYTES>>>(
        (const float*)d_in[0], (const int*)d_in[1], (const float*)d_in[2],
        (const float*)d_in[3], (const float*)d_in[4], (const float*)d_in[5], (const float*)d_in[6],
        (const float*)d_in[11], outp, starp);
}